// round 13
// baseline (speedup 1.0000x reference)
#include <cuda_runtime.h>
#include <cuda_fp16.h>
#include <cstdint>

// Problem constants
#define NB   8
#define NH   8
#define SEQ  2048
#define HD   64
#define EMB  512
#define BH   (NB * NH)          // 64
#define NROWS (BH * SEQ)        // 131072

#define PITCH 68                // fp32 smem pitch (proj kernel)
#define P4    17
#define PH    72                // half smem pitch (72 halves = 144 B)
#define VT_P  136               // V-transpose staging pitch (halves)

// Scratch (__device__ globals)
static __device__ __align__(256) __half g_QPh[BH * SEQ * HD];  // [bh][l][d], Qm scaled by log2(e)/sqrt(512)
static __device__ __align__(256) __half g_KPh[BH * SEQ * HD];  // [bh][l][d]  (raw key, converted)
static __device__ __align__(256) __half g_VPt[BH * HD * SEQ];  // [bh][d][l]  (transposed)
static __device__ __align__(256) __half g_AOh[NB * SEQ * EMB]; // [b][l][e]
static __device__ __align__(256) __half g_Woh[EMB * EMB];      // Wo as half
static __device__ __align__(256) float  g_Wqk[HD * HD];        // (Wq^T Wk) arranged [n][k]

__device__ __forceinline__ float tf32r(float x) {
    uint32_t u;
    asm("cvt.rna.tf32.f32 %0, %1;" : "=r"(u) : "f"(x));
    return __uint_as_float(u);
}
__device__ __forceinline__ uint32_t f22h(float lo, float hi) {
    __half2 h = __floats2half2_rn(lo, hi);
    return *reinterpret_cast<uint32_t*>(&h);
}
__device__ __forceinline__ uint32_t h2u(__half2 h) {
    return *reinterpret_cast<uint32_t*>(&h);
}
__device__ __forceinline__ __half2 u2h(uint32_t u) {
    return *reinterpret_cast<__half2*>(&u);
}

// tf32 mma (proj only)
__device__ __forceinline__ void mma8(float& c0, float& c1, float& c2, float& c3,
                                     float a0, float a1, float a2, float a3,
                                     float b0, float b1) {
    asm volatile(
        "mma.sync.aligned.m16n8k8.row.col.f32.tf32.tf32.f32 "
        "{%0,%1,%2,%3}, {%4,%5,%6,%7}, {%8,%9}, {%0,%1,%2,%3};\n"
        : "+f"(c0), "+f"(c1), "+f"(c2), "+f"(c3)
        : "r"(__float_as_uint(a0)), "r"(__float_as_uint(a1)),
          "r"(__float_as_uint(a2)), "r"(__float_as_uint(a3)),
          "r"(__float_as_uint(b0)), "r"(__float_as_uint(b1)));
}
// fp16 mma, f32 accum
__device__ __forceinline__ void mma16(float& c0, float& c1, float& c2, float& c3,
                                      uint32_t a0, uint32_t a1, uint32_t a2, uint32_t a3,
                                      uint32_t b0, uint32_t b1) {
    asm volatile(
        "mma.sync.aligned.m16n8k16.row.col.f32.f16.f16.f32 "
        "{%0,%1,%2,%3}, {%4,%5,%6,%7}, {%8,%9}, {%0,%1,%2,%3};\n"
        : "+f"(c0), "+f"(c1), "+f"(c2), "+f"(c3)
        : "r"(a0), "r"(a1), "r"(a2), "r"(a3), "r"(b0), "r"(b1));
}
// fp16 mma, f16 accum (QK path)
__device__ __forceinline__ void mma16h(uint32_t& c0, uint32_t& c1,
                                       uint32_t a0, uint32_t a1, uint32_t a2, uint32_t a3,
                                       uint32_t b0, uint32_t b1) {
    asm volatile(
        "mma.sync.aligned.m16n8k16.row.col.f16.f16.f16.f16 "
        "{%0,%1}, {%2,%3,%4,%5}, {%6,%7}, {%0,%1};\n"
        : "+r"(c0), "+r"(c1)
        : "r"(a0), "r"(a1), "r"(a2), "r"(a3), "r"(b0), "r"(b1));
}

__device__ __forceinline__ void ldsm4(uint32_t& r0, uint32_t& r1, uint32_t& r2, uint32_t& r3,
                                      uint32_t a) {
    asm volatile("ldmatrix.sync.aligned.m8n8.x4.shared.b16 {%0,%1,%2,%3}, [%4];"
                 : "=r"(r0), "=r"(r1), "=r"(r2), "=r"(r3) : "r"(a));
}

__device__ __forceinline__ void cp16(uint32_t dst, const void* src) {
    asm volatile("cp.async.cg.shared.global [%0], [%1], 16;" :: "r"(dst), "l"(src));
}
__device__ __forceinline__ void cp_commit() { asm volatile("cp.async.commit_group;"); }
__device__ __forceinline__ void cp_wait0()  { asm volatile("cp.async.wait_group 0;"); }
__device__ __forceinline__ void cp_wait1()  { asm volatile("cp.async.wait_group 1;"); }
__device__ __forceinline__ void cp_wait2()  { asm volatile("cp.async.wait_group 2;"); }

// ---------------------------------------------------------------------------
// Kernel 0a: Wo fp32 -> half
// ---------------------------------------------------------------------------
__global__ __launch_bounds__(256) void conv_wo_kernel(const float* __restrict__ Wo) {
    int i = blockIdx.x * 256 + threadIdx.x;        // 65536 float4s
    float4 w = ((const float4*)Wo)[i];
    uint2 p;
    p.x = f22h(w.x, w.y);
    p.y = f22h(w.z, w.w);
    ((uint2*)g_Woh)[i] = p;
}

// ---------------------------------------------------------------------------
// Kernel 0b: fold M_eff[n][k] = (Wq^T Wk)[k][n]
// ---------------------------------------------------------------------------
__global__ __launch_bounds__(256) void m_fold_kernel(
    const float* __restrict__ Wq, const float* __restrict__ Wk) {
    int idx = blockIdx.x * 256 + threadIdx.x;      // 0..4095
    int n = idx >> 6, k = idx & 63;
    float s = 0.f;
    #pragma unroll 8
    for (int t = 0; t < 64; ++t)
        s += Wq[t * 64 + k] * Wk[t * 64 + n];
    g_Wqk[idx] = s;
}

// ---------------------------------------------------------------------------
// Kernel 1: projections (identical to best build).
// ---------------------------------------------------------------------------
__global__ __launch_bounds__(128) void proj_kernel(
    const float* __restrict__ Qin, const float* __restrict__ Kin,
    const float* __restrict__ Vin, const float* __restrict__ Wv)
{
    extern __shared__ float sm[];
    float* Xs = sm;                 // 128 x PITCH
    float* Ws = sm + 128 * PITCH;   // 64 x PITCH

    const int tid  = threadIdx.x;
    const int which = blockIdx.y;
    const int r0 = blockIdx.x * 128;

    if (which == 1) {
        const float4* X4 = (const float4*)(Kin + (size_t)r0 * HD);
        uint2* O2 = (uint2*)(g_KPh + (size_t)r0 * HD);
        #pragma unroll
        for (int i = 0; i < 16; ++i) {
            int g = tid + i * 128;
            float4 v = X4[g];
            uint2 p;
            p.x = f22h(v.x, v.y);
            p.y = f22h(v.z, v.w);
            O2[g] = p;
        }
        return;
    }

    const int lane = tid & 31, wm = tid >> 5;
    const int gid  = lane >> 2, qid = lane & 3;
    const float* W = (which == 0) ? g_Wqk : Wv;

    const float4* W4 = (const float4*)W;
    #pragma unroll
    for (int i = 0; i < 8; ++i) {
        int g = tid + i * 128;
        float4 w = W4[g];
        w.x = tf32r(w.x); w.y = tf32r(w.y); w.z = tf32r(w.z); w.w = tf32r(w.w);
        ((float4*)Ws)[(g >> 4) * P4 + (g & 15)] = w;
    }
    if (which == 0) {
        const float4* X4 = (const float4*)(Qin + (size_t)r0 * HD);
        #pragma unroll
        for (int i = 0; i < 16; ++i) {
            int g = tid + i * 128;
            float4 v = X4[g];
            v.x = tf32r(v.x); v.y = tf32r(v.y); v.z = tf32r(v.z); v.w = tf32r(v.w);
            ((float4*)Xs)[(g >> 4) * P4 + (g & 15)] = v;
        }
    } else {
        const int bh = r0 >> 11, l0 = r0 & 2047;
        const int b = bh >> 3, h = bh & 7;
        const float* base = Vin + ((size_t)(b * SEQ + l0)) * EMB + h * HD;
        #pragma unroll
        for (int i = 0; i < 16; ++i) {
            int g = tid + i * 128;
            int r = g >> 4, c4 = g & 15;
            float4 v = *(const float4*)(base + (size_t)r * EMB + c4 * 4);
            v.x = tf32r(v.x); v.y = tf32r(v.y); v.z = tf32r(v.z); v.w = tf32r(v.w);
            ((float4*)Xs)[r * P4 + c4] = v;
        }
    }
    __syncthreads();

    float o[2][8][4];
    #pragma unroll
    for (int mi = 0; mi < 2; ++mi)
        #pragma unroll
        for (int ni = 0; ni < 8; ++ni)
            #pragma unroll
            for (int t = 0; t < 4; ++t) o[mi][ni][t] = 0.f;

    #pragma unroll
    for (int ks = 0; ks < 8; ++ks) {
        float a[2][4];
        #pragma unroll
        for (int mi = 0; mi < 2; ++mi) {
            int r = 32 * wm + 16 * mi + gid;
            int c = ks * 8 + qid;
            a[mi][0] = Xs[r * PITCH + c];
            a[mi][1] = Xs[(r + 8) * PITCH + c];
            a[mi][2] = Xs[r * PITCH + c + 4];
            a[mi][3] = Xs[(r + 8) * PITCH + c + 4];
        }
        #pragma unroll
        for (int ni = 0; ni < 8; ++ni) {
            float b0 = Ws[(ni * 8 + gid) * PITCH + ks * 8 + qid];
            float b1 = Ws[(ni * 8 + gid) * PITCH + ks * 8 + qid + 4];
            #pragma unroll
            for (int mi = 0; mi < 2; ++mi)
                mma8(o[mi][ni][0], o[mi][ni][1], o[mi][ni][2], o[mi][ni][3],
                     a[mi][0], a[mi][1], a[mi][2], a[mi][3], b0, b1);
        }
    }

    const float qscale = 0.06375863286367196f;
    if (which == 0) {
        #pragma unroll
        for (int mi = 0; mi < 2; ++mi) {
            int r = r0 + 32 * wm + 16 * mi + gid;
            #pragma unroll
            for (int ni = 0; ni < 8; ++ni) {
                int c = ni * 8 + 2 * qid;
                *(uint32_t*)(g_QPh + (size_t)r * HD + c) =
                    f22h(o[mi][ni][0] * qscale, o[mi][ni][1] * qscale);
                *(uint32_t*)(g_QPh + (size_t)(r + 8) * HD + c) =
                    f22h(o[mi][ni][2] * qscale, o[mi][ni][3] * qscale);
            }
        }
    } else {
        const int bh = r0 >> 11;
        const size_t base = (size_t)bh * HD * SEQ;
        const int l0 = (r0 & 2047);
        __half* Vt = (__half*)sm;                  // 64 x VT_P halves
        __syncthreads();
        #pragma unroll
        for (int mi = 0; mi < 2; ++mi) {
            int l = 32 * wm + 16 * mi + gid;
            #pragma unroll
            for (int ni = 0; ni < 8; ++ni) {
                int c = ni * 8 + 2 * qid;
                Vt[c * VT_P + l]           = __float2half_rn(o[mi][ni][0]);
                Vt[(c + 1) * VT_P + l]     = __float2half_rn(o[mi][ni][1]);
                Vt[c * VT_P + l + 8]       = __float2half_rn(o[mi][ni][2]);
                Vt[(c + 1) * VT_P + l + 8] = __float2half_rn(o[mi][ni][3]);
            }
        }
        __syncthreads();
        #pragma unroll
        for (int p = 0; p < 16; ++p) {
            int d = p * 4 + wm;
            uint2 v = *(const uint2*)(Vt + d * VT_P + lane * 4);
            *(uint2*)(g_VPt + base + (size_t)d * SEQ + l0 + lane * 4) = v;
        }
    }
}

// ---------------------------------------------------------------------------
// Kernel 2: fp16 flash attention, no-max softmax, fp16-accum QK,
// SOFTWARE-PIPELINED: iteration = softmax(t) -> PV(t) -> QK(t+1).
// S double-buffered; P computed in place in the S buffer.
// grid (SEQ/128, BH), block 128, dyn smem 73728 B, 2 CTAs/SM.
// ---------------------------------------------------------------------------
__global__ __launch_bounds__(128, 2) void attn_kernel()
{
    extern __shared__ __align__(16) unsigned char smraw[];
    __half* KV = (__half*)smraw;     // 4 stages x (K 64xPH + V 64xPH)

    const int tid  = threadIdx.x;
    const int lane = tid & 31, wm = tid >> 5;      // wm 0..3
    const int gid  = lane >> 2, qid = lane & 3;
    const int bh = blockIdx.y;
    const int q0 = blockIdx.x * 128;

    const uint32_t kv_smem = (uint32_t)__cvta_generic_to_shared(KV);
    const int TILE_H = 64 * PH;
    const int TILE_B = TILE_H * 2;       // 9216 B
    const int NT = SEQ / 64;             // 32

    const __half* Kg0 = g_KPh + (size_t)bh * SEQ * HD;
    const __half* Vg0 = g_VPt + (size_t)bh * HD * SEQ;

    const uint32_t lane_off =
        (uint32_t)((((lane & 7) + ((lane >> 4) << 3)) * PH + ((lane >> 3) & 1) * 8) * 2);

    auto prefetch = [&](int tt) {
        uint32_t base = kv_smem + (uint32_t)((tt & 3) * 2 * TILE_B);
        const __half* Kg = Kg0 + (size_t)tt * 64 * HD;
        const __half* Vg = Vg0 + tt * 64;
        #pragma unroll
        for (int i = 0; i < 4; ++i) {
            int g = tid + i * 128;
            int row = g >> 3, c8 = g & 7;
            uint32_t off = (uint32_t)(row * 144 + c8 * 16);
            cp16(base + off, Kg + (size_t)row * HD + c8 * 8);
            cp16(base + (uint32_t)TILE_B + off, Vg + (size_t)row * SEQ + c8 * 8);
        }
        cp_commit();
    };

    // prefetch tiles 0,1,2
    prefetch(0); prefetch(1); prefetch(2);

    // Q fragments straight from gmem (pre-scaled half)
    uint32_t qf[2][4][4];
    {
        const __half* Qg = g_QPh + (size_t)(bh * SEQ + q0 + 32 * wm + gid) * HD;
        #pragma unroll
        for (int mi = 0; mi < 2; ++mi) {
            const __half* Qm = Qg + (size_t)(16 * mi) * HD;
            #pragma unroll
            for (int kt = 0; kt < 4; ++kt) {
                int c = kt * 16 + 2 * qid;
                qf[mi][kt][0] = *(const uint32_t*)(Qm + c);
                qf[mi][kt][1] = *(const uint32_t*)(Qm + 8 * HD + c);
                qf[mi][kt][2] = *(const uint32_t*)(Qm + c + 8);
                qf[mi][kt][3] = *(const uint32_t*)(Qm + 8 * HD + c + 8);
            }
        }
    }

    float o[2][8][4];
    #pragma unroll
    for (int mi = 0; mi < 2; ++mi)
        #pragma unroll
        for (int ni = 0; ni < 8; ++ni)
            #pragma unroll
            for (int t = 0; t < 4; ++t) o[mi][ni][t] = 0.f;
    float lsum[2][2] = {{0.f, 0.f}, {0.f, 0.f}};

    uint32_t sA[2][8][2], sB[2][8][2];

    // QK into a given buffer for tile tt
    auto qk = [&](int tt, uint32_t (&sn)[2][8][2]) {
        #pragma unroll
        for (int mi = 0; mi < 2; ++mi)
            #pragma unroll
            for (int ni = 0; ni < 8; ++ni) {
                sn[mi][ni][0] = 0u;
                sn[mi][ni][1] = 0u;
            }
        const uint32_t KsS = kv_smem + (uint32_t)((tt & 3) * 2 * TILE_B) + lane_off;
        #pragma unroll
        for (int kt = 0; kt < 4; ++kt) {
            #pragma unroll
            for (int nip = 0; nip < 4; ++nip) {
                uint32_t b0, b1, b2, b3;
                ldsm4(b0, b1, b2, b3, KsS + (uint32_t)((nip * 16 * PH + kt * 16) * 2));
                #pragma unroll
                for (int mi = 0; mi < 2; ++mi) {
                    mma16h(sn[mi][2 * nip][0], sn[mi][2 * nip][1],
                           qf[mi][kt][0], qf[mi][kt][1], qf[mi][kt][2], qf[mi][kt][3], b0, b1);
                    mma16h(sn[mi][2 * nip + 1][0], sn[mi][2 * nip + 1][1],
                           qf[mi][kt][0], qf[mi][kt][1], qf[mi][kt][2], qf[mi][kt][3], b2, b3);
                }
            }
        }
    };

    // softmax in place: P = exp2(S), accumulate row-sum partials
    auto softmax = [&](uint32_t (&sp)[2][8][2]) {
        #pragma unroll
        for (int mi = 0; mi < 2; ++mi) {
            #pragma unroll
            for (int ni = 0; ni < 8; ++ni) {
                sp[mi][ni][0] = h2u(h2exp2(u2h(sp[mi][ni][0])));
                sp[mi][ni][1] = h2u(h2exp2(u2h(sp[mi][ni][1])));
            }
            __half2 s0t = __hadd2(
                __hadd2(__hadd2(u2h(sp[mi][0][0]), u2h(sp[mi][1][0])),
                        __hadd2(u2h(sp[mi][2][0]), u2h(sp[mi][3][0]))),
                __hadd2(__hadd2(u2h(sp[mi][4][0]), u2h(sp[mi][5][0])),
                        __hadd2(u2h(sp[mi][6][0]), u2h(sp[mi][7][0]))));
            __half2 s1t = __hadd2(
                __hadd2(__hadd2(u2h(sp[mi][0][1]), u2h(sp[mi][1][1])),
                        __hadd2(u2h(sp[mi][2][1]), u2h(sp[mi][3][1]))),
                __hadd2(__hadd2(u2h(sp[mi][4][1]), u2h(sp[mi][5][1])),
                        __hadd2(u2h(sp[mi][6][1]), u2h(sp[mi][7][1]))));
            float2 s0f = __half22float2(s0t);
            float2 s1f = __half22float2(s1t);
            lsum[mi][0] += s0f.x + s0f.y;
            lsum[mi][1] += s1f.x + s1f.y;
        }
    };

    // O += P(t) V(t); P lives in the S buffer
    auto pv = [&](int tt, uint32_t (&sp)[2][8][2]) {
        const uint32_t VsS = kv_smem + (uint32_t)((tt & 3) * 2 * TILE_B)
                           + (uint32_t)TILE_B + lane_off;
        #pragma unroll
        for (int kt = 0; kt < 4; ++kt) {
            #pragma unroll
            for (int nip = 0; nip < 4; ++nip) {
                uint32_t v0, v1, v2, v3;
                ldsm4(v0, v1, v2, v3, VsS + (uint32_t)((nip * 16 * PH + kt * 16) * 2));
                #pragma unroll
                for (int mi = 0; mi < 2; ++mi) {
                    mma16(o[mi][2 * nip][0], o[mi][2 * nip][1],
                          o[mi][2 * nip][2], o[mi][2 * nip][3],
                          sp[mi][2 * kt][0], sp[mi][2 * kt][1],
                          sp[mi][2 * kt + 1][0], sp[mi][2 * kt + 1][1], v0, v1);
                    mma16(o[mi][2 * nip + 1][0], o[mi][2 * nip + 1][1],
                          o[mi][2 * nip + 1][2], o[mi][2 * nip + 1][3],
                          sp[mi][2 * kt][0], sp[mi][2 * kt][1],
                          sp[mi][2 * kt + 1][0], sp[mi][2 * kt + 1][1], v2, v3);
                }
            }
        }
    };

    // preloop: QK(0)
    cp_wait2();
    __syncthreads();
    qk(0, sA);

    for (int t = 0; t < NT; t += 2) {
        // sub-iter A: tile t (always t+1 < NT here)
        {
            if (t + 2 < NT) cp_wait1(); else cp_wait0();
            __syncthreads();                       // readers of stage t-1 done
            if (t + 3 < NT) prefetch(t + 3);
            softmax(sA);
            pv(t, sA);
            qk(t + 1, sB);
        }
        // sub-iter B: tile t+1
        {
            const int u = t + 1;
            if (u + 2 < NT) cp_wait1(); else if (u + 1 < NT) cp_wait0();
            __syncthreads();
            if (u + 3 < NT) prefetch(u + 3);
            softmax(sB);
            pv(u, sB);
            if (u + 1 < NT) qk(u + 1, sA);
        }
    }

    // epilogue: reduce l across the qid quad, normalize, store half
    const int b = bh >> 3, hh = bh & 7;
    #pragma unroll
    for (int mi = 0; mi < 2; ++mi) {
        float l0 = lsum[mi][0], l1 = lsum[mi][1];
        l0 += __shfl_xor_sync(0xffffffffu, l0, 1);
        l0 += __shfl_xor_sync(0xffffffffu, l0, 2);
        l1 += __shfl_xor_sync(0xffffffffu, l1, 1);
        l1 += __shfl_xor_sync(0xffffffffu, l1, 2);
        const float inv0 = 1.0f / l0;
        const float inv1 = 1.0f / l1;
        const int r = q0 + 32 * wm + 16 * mi + gid;
        #pragma unroll
        for (int ni = 0; ni < 8; ++ni) {
            int c = ni * 8 + 2 * qid;
            *(uint32_t*)(g_AOh + (size_t)(b * SEQ + r) * EMB + hh * HD + c) =
                f22h(o[mi][ni][0] * inv0, o[mi][ni][1] * inv0);
            *(uint32_t*)(g_AOh + (size_t)(b * SEQ + r + 8) * EMB + hh * HD + c) =
                f22h(o[mi][ni][2] * inv1, o[mi][ni][3] * inv1);
        }
    }
}

// ---------------------------------------------------------------------------
// Kernel 3: out = AOh @ Woh^T + bo  (identical to best build)
// ---------------------------------------------------------------------------
__global__ __launch_bounds__(128, 3) void out_proj_kernel(
    const float* __restrict__ bo, float* __restrict__ out)
{
    extern __shared__ __align__(16) unsigned char smraw[];
    const int tid  = threadIdx.x;
    const int lane = tid & 31, wm = tid >> 5;
    const int gid  = lane >> 2, qid = lane & 3;
    const int m0 = blockIdx.x * 128;
    const int n0 = blockIdx.y * 64;

    const uint32_t sm0 = (uint32_t)__cvta_generic_to_shared(smraw);
    const int BUF_B = (128 + 64) * 144;   // 27648 B

    auto prefetch = [&](int c) {
        uint32_t base = sm0 + (uint32_t)((c & 1) * BUF_B);
        int k0 = c * 64;
        #pragma unroll
        for (int i = 0; i < 8; ++i) {
            int g = tid + i * 128;
            int row = g >> 3, c8 = g & 7;
            cp16(base + (uint32_t)(row * 144 + c8 * 16),
                 g_AOh + (size_t)(m0 + row) * EMB + k0 + c8 * 8);
        }
        #pragma unroll
        for (int i = 0; i < 4; ++i) {
            int g = tid + i * 128;
            int row = g >> 3, c8 = g & 7;
            cp16(base + (uint32_t)(128 * 144 + row * 144 + c8 * 16),
                 g_Woh + (size_t)(n0 + row) * EMB + k0 + c8 * 8);
        }
        cp_commit();
    };

    prefetch(0);

    float o[2][8][4];
    #pragma unroll
    for (int mi = 0; mi < 2; ++mi)
        #pragma unroll
        for (int ni = 0; ni < 8; ++ni)
            #pragma unroll
            for (int t = 0; t < 4; ++t) o[mi][ni][t] = 0.f;

    const uint32_t laneA = (uint32_t)(((lane & 15) * PH + (lane >> 4) * 8) * 2);
    const uint32_t laneB =
        (uint32_t)((((lane & 7) + ((lane >> 4) << 3)) * PH + ((lane >> 3) & 1) * 8) * 2);

    for (int c = 0; c < 8; ++c) {
        cp_wait0();
        __syncthreads();
        if (c + 1 < 8) prefetch(c + 1);

        uint32_t AsS = sm0 + (uint32_t)((c & 1) * BUF_B) + laneA;
        uint32_t BsS = sm0 + (uint32_t)((c & 1) * BUF_B + 128 * 144) + laneB;

        #pragma unroll
        for (int kt = 0; kt < 4; ++kt) {
            uint32_t a[2][4];
            #pragma unroll
            for (int mi = 0; mi < 2; ++mi)
                ldsm4(a[mi][0], a[mi][1], a[mi][2], a[mi][3],
                      AsS + (uint32_t)((((32 * wm + 16 * mi) * PH) + kt * 16) * 2));
            #pragma unroll
            for (int nip = 0; nip < 4; ++nip) {
                uint32_t b0, b1, b2, b3;
                ldsm4(b0, b1, b2, b3,
                      BsS + (uint32_t)(((nip * 16 * PH) + kt * 16) * 2));
                #pragma unroll
                for (int mi = 0; mi < 2; ++mi) {
                    mma16(o[mi][2 * nip][0], o[mi][2 * nip][1],
                          o[mi][2 * nip][2], o[mi][2 * nip][3],
                          a[mi][0], a[mi][1], a[mi][2], a[mi][3], b0, b1);
                    mma16(o[mi][2 * nip + 1][0], o[mi][2 * nip + 1][1],
                          o[mi][2 * nip + 1][2], o[mi][2 * nip + 1][3],
                          a[mi][0], a[mi][1], a[mi][2], a[mi][3], b2, b3);
                }
            }
        }
    }

    #pragma unroll
    for (int mi = 0; mi < 2; ++mi) {
        int r = m0 + 32 * wm + 16 * mi + gid;
        #pragma unroll
        for (int ni = 0; ni < 8; ++ni) {
            int cc = n0 + ni * 8 + 2 * qid;
            float bb0 = bo[cc], bb1 = bo[cc + 1];
            *(float2*)(out + (size_t)r * EMB + cc) =
                make_float2(o[mi][ni][0] + bb0, o[mi][ni][1] + bb1);
            *(float2*)(out + (size_t)(r + 8) * EMB + cc) =
                make_float2(o[mi][ni][2] + bb0, o[mi][ni][3] + bb1);
        }
    }
}

// ---------------------------------------------------------------------------
extern "C" void kernel_launch(void* const* d_in, const int* in_sizes, int n_in,
                              void* d_out, int out_size)
{
    const float* q  = (const float*)d_in[0];
    const float* k  = (const float*)d_in[1];
    const float* v  = (const float*)d_in[2];
    const float* Wq = (const float*)d_in[3];
    const float* Wk = (const float*)d_in[4];
    const float* Wv = (const float*)d_in[5];
    const float* Wo = (const float*)d_in[6];
    const float* bo = (const float*)d_in[7];
    float* out = (float*)d_out;

    const int proj_smem  = (128 * PITCH + 64 * PITCH) * (int)sizeof(float);   // 52224
    const int attn_smem  = 4 * 2 * 64 * PH * 2;                               // 73728
    const int oproj_smem = 2 * (128 + 64) * 144;                              // 55296

    cudaFuncSetAttribute(proj_kernel, cudaFuncAttributeMaxDynamicSharedMemorySize, proj_smem);
    cudaFuncSetAttribute(attn_kernel, cudaFuncAttributeMaxDynamicSharedMemorySize, attn_smem);
    cudaFuncSetAttribute(out_proj_kernel, cudaFuncAttributeMaxDynamicSharedMemorySize, oproj_smem);

    conv_wo_kernel<<<256, 256>>>(Wo);
    m_fold_kernel<<<16, 256>>>(Wq, Wk);
    proj_kernel<<<dim3(NROWS / 128, 3, 1), 128, proj_smem>>>(q, k, v, Wv);
    attn_kernel<<<dim3(SEQ / 128, BH, 1), 128, attn_smem>>>();
    out_proj_kernel<<<dim3((NB * SEQ) / 128, EMB / 64, 1), 128, oproj_smem>>>(bo, out);
}

// round 14
// speedup vs baseline: 1.4875x; 1.4875x over previous
#include <cuda_runtime.h>
#include <cuda_fp16.h>
#include <cstdint>

// Problem constants
#define NB   8
#define NH   8
#define SEQ  2048
#define HD   64
#define EMB  512
#define BH   (NB * NH)          // 64
#define NROWS (BH * SEQ)        // 131072

#define PITCH 68                // fp32 smem pitch (proj kernel)
#define P4    17
#define PH    72                // half smem pitch (72 halves = 144 B)
#define VT_P  136               // V-transpose staging pitch (halves)

// Scratch (__device__ globals)
static __device__ __align__(256) __half g_QPh[BH * SEQ * HD];  // [bh][l][d], Qm scaled by log2(e)/sqrt(512)
static __device__ __align__(256) __half g_KPh[BH * SEQ * HD];  // [bh][l][d]  (raw key, converted)
static __device__ __align__(256) __half g_VPt[BH * HD * SEQ];  // [bh][d][l]  (transposed)
static __device__ __align__(256) __half g_AOh[NB * SEQ * EMB]; // [b][l][e]
static __device__ __align__(256) __half g_Woh[EMB * EMB];      // Wo as half
static __device__ __align__(256) float  g_Wqk[HD * HD];        // (Wq^T Wk) arranged [n][k]

__device__ __forceinline__ float tf32r(float x) {
    uint32_t u;
    asm("cvt.rna.tf32.f32 %0, %1;" : "=r"(u) : "f"(x));
    return __uint_as_float(u);
}
__device__ __forceinline__ uint32_t f22h(float lo, float hi) {
    __half2 h = __floats2half2_rn(lo, hi);
    return *reinterpret_cast<uint32_t*>(&h);
}
__device__ __forceinline__ uint32_t h2u(__half2 h) {
    return *reinterpret_cast<uint32_t*>(&h);
}
__device__ __forceinline__ __half2 u2h(uint32_t u) {
    return *reinterpret_cast<__half2*>(&u);
}

// tf32 mma (proj only)
__device__ __forceinline__ void mma8(float& c0, float& c1, float& c2, float& c3,
                                     float a0, float a1, float a2, float a3,
                                     float b0, float b1) {
    asm volatile(
        "mma.sync.aligned.m16n8k8.row.col.f32.tf32.tf32.f32 "
        "{%0,%1,%2,%3}, {%4,%5,%6,%7}, {%8,%9}, {%0,%1,%2,%3};\n"
        : "+f"(c0), "+f"(c1), "+f"(c2), "+f"(c3)
        : "r"(__float_as_uint(a0)), "r"(__float_as_uint(a1)),
          "r"(__float_as_uint(a2)), "r"(__float_as_uint(a3)),
          "r"(__float_as_uint(b0)), "r"(__float_as_uint(b1)));
}
// fp16 mma, f32 accum
__device__ __forceinline__ void mma16(float& c0, float& c1, float& c2, float& c3,
                                      uint32_t a0, uint32_t a1, uint32_t a2, uint32_t a3,
                                      uint32_t b0, uint32_t b1) {
    asm volatile(
        "mma.sync.aligned.m16n8k16.row.col.f32.f16.f16.f32 "
        "{%0,%1,%2,%3}, {%4,%5,%6,%7}, {%8,%9}, {%0,%1,%2,%3};\n"
        : "+f"(c0), "+f"(c1), "+f"(c2), "+f"(c3)
        : "r"(a0), "r"(a1), "r"(a2), "r"(a3), "r"(b0), "r"(b1));
}
// fp16 mma, f16 accum (QK path: S emerges pre-packed as half2)
__device__ __forceinline__ void mma16h(uint32_t& c0, uint32_t& c1,
                                       uint32_t a0, uint32_t a1, uint32_t a2, uint32_t a3,
                                       uint32_t b0, uint32_t b1) {
    asm volatile(
        "mma.sync.aligned.m16n8k16.row.col.f16.f16.f16.f16 "
        "{%0,%1}, {%2,%3,%4,%5}, {%6,%7}, {%0,%1};\n"
        : "+r"(c0), "+r"(c1)
        : "r"(a0), "r"(a1), "r"(a2), "r"(a3), "r"(b0), "r"(b1));
}

__device__ __forceinline__ void ldsm4(uint32_t& r0, uint32_t& r1, uint32_t& r2, uint32_t& r3,
                                      uint32_t a) {
    asm volatile("ldmatrix.sync.aligned.m8n8.x4.shared.b16 {%0,%1,%2,%3}, [%4];"
                 : "=r"(r0), "=r"(r1), "=r"(r2), "=r"(r3) : "r"(a));
}

__device__ __forceinline__ void cp16(uint32_t dst, const void* src) {
    asm volatile("cp.async.cg.shared.global [%0], [%1], 16;" :: "r"(dst), "l"(src));
}
__device__ __forceinline__ void cp_commit() { asm volatile("cp.async.commit_group;"); }
__device__ __forceinline__ void cp_wait0()  { asm volatile("cp.async.wait_group 0;"); }
__device__ __forceinline__ void cp_wait1()  { asm volatile("cp.async.wait_group 1;"); }
__device__ __forceinline__ void cp_wait2()  { asm volatile("cp.async.wait_group 2;"); }

// ---------------------------------------------------------------------------
// Kernel 0a: Wo fp32 -> half
// ---------------------------------------------------------------------------
__global__ __launch_bounds__(256) void conv_wo_kernel(const float* __restrict__ Wo) {
    int i = blockIdx.x * 256 + threadIdx.x;        // 65536 float4s
    float4 w = ((const float4*)Wo)[i];
    uint2 p;
    p.x = f22h(w.x, w.y);
    p.y = f22h(w.z, w.w);
    ((uint2*)g_Woh)[i] = p;
}

// ---------------------------------------------------------------------------
// Kernel 0b: fold M_eff[n][k] = (Wq^T Wk)[k][n]
// ---------------------------------------------------------------------------
__global__ __launch_bounds__(256) void m_fold_kernel(
    const float* __restrict__ Wq, const float* __restrict__ Wk) {
    int idx = blockIdx.x * 256 + threadIdx.x;      // 0..4095
    int n = idx >> 6, k = idx & 63;
    float s = 0.f;
    #pragma unroll 8
    for (int t = 0; t < 64; ++t)
        s += Wq[t * 64 + k] * Wk[t * 64 + n];
    g_Wqk[idx] = s;
}

// ---------------------------------------------------------------------------
// Kernel 1: projections.
//  which 0: Qm = Xq @ (Wq^T Wk)  (tf32 mma, scaled)  -> g_QPh
//  which 1: pure convert raw key -> g_KPh
//  which 2: V proj (tf32 mma) -> g_VPt via coalesced smem transpose
// grid (NROWS/128, 3), block 128
// ---------------------------------------------------------------------------
__global__ __launch_bounds__(128) void proj_kernel(
    const float* __restrict__ Qin, const float* __restrict__ Kin,
    const float* __restrict__ Vin, const float* __restrict__ Wv)
{
    extern __shared__ float sm[];
    float* Xs = sm;                 // 128 x PITCH
    float* Ws = sm + 128 * PITCH;   // 64 x PITCH

    const int tid  = threadIdx.x;
    const int which = blockIdx.y;
    const int r0 = blockIdx.x * 128;

    if (which == 1) {
        const float4* X4 = (const float4*)(Kin + (size_t)r0 * HD);
        uint2* O2 = (uint2*)(g_KPh + (size_t)r0 * HD);
        #pragma unroll
        for (int i = 0; i < 16; ++i) {
            int g = tid + i * 128;
            float4 v = X4[g];
            uint2 p;
            p.x = f22h(v.x, v.y);
            p.y = f22h(v.z, v.w);
            O2[g] = p;
        }
        return;
    }

    const int lane = tid & 31, wm = tid >> 5;
    const int gid  = lane >> 2, qid = lane & 3;
    const float* W = (which == 0) ? g_Wqk : Wv;

    const float4* W4 = (const float4*)W;
    #pragma unroll
    for (int i = 0; i < 8; ++i) {
        int g = tid + i * 128;
        float4 w = W4[g];
        w.x = tf32r(w.x); w.y = tf32r(w.y); w.z = tf32r(w.z); w.w = tf32r(w.w);
        ((float4*)Ws)[(g >> 4) * P4 + (g & 15)] = w;
    }
    if (which == 0) {
        const float4* X4 = (const float4*)(Qin + (size_t)r0 * HD);
        #pragma unroll
        for (int i = 0; i < 16; ++i) {
            int g = tid + i * 128;
            float4 v = X4[g];
            v.x = tf32r(v.x); v.y = tf32r(v.y); v.z = tf32r(v.z); v.w = tf32r(v.w);
            ((float4*)Xs)[(g >> 4) * P4 + (g & 15)] = v;
        }
    } else {
        const int bh = r0 >> 11, l0 = r0 & 2047;
        const int b = bh >> 3, h = bh & 7;
        const float* base = Vin + ((size_t)(b * SEQ + l0)) * EMB + h * HD;
        #pragma unroll
        for (int i = 0; i < 16; ++i) {
            int g = tid + i * 128;
            int r = g >> 4, c4 = g & 15;
            float4 v = *(const float4*)(base + (size_t)r * EMB + c4 * 4);
            v.x = tf32r(v.x); v.y = tf32r(v.y); v.z = tf32r(v.z); v.w = tf32r(v.w);
            ((float4*)Xs)[r * P4 + c4] = v;
        }
    }
    __syncthreads();

    float o[2][8][4];
    #pragma unroll
    for (int mi = 0; mi < 2; ++mi)
        #pragma unroll
        for (int ni = 0; ni < 8; ++ni)
            #pragma unroll
            for (int t = 0; t < 4; ++t) o[mi][ni][t] = 0.f;

    #pragma unroll
    for (int ks = 0; ks < 8; ++ks) {
        float a[2][4];
        #pragma unroll
        for (int mi = 0; mi < 2; ++mi) {
            int r = 32 * wm + 16 * mi + gid;
            int c = ks * 8 + qid;
            a[mi][0] = Xs[r * PITCH + c];
            a[mi][1] = Xs[(r + 8) * PITCH + c];
            a[mi][2] = Xs[r * PITCH + c + 4];
            a[mi][3] = Xs[(r + 8) * PITCH + c + 4];
        }
        #pragma unroll
        for (int ni = 0; ni < 8; ++ni) {
            float b0 = Ws[(ni * 8 + gid) * PITCH + ks * 8 + qid];
            float b1 = Ws[(ni * 8 + gid) * PITCH + ks * 8 + qid + 4];
            #pragma unroll
            for (int mi = 0; mi < 2; ++mi)
                mma8(o[mi][ni][0], o[mi][ni][1], o[mi][ni][2], o[mi][ni][3],
                     a[mi][0], a[mi][1], a[mi][2], a[mi][3], b0, b1);
        }
    }

    // 1/sqrt(512) * log2(e): softmax computed in base-2
    const float qscale = 0.06375863286367196f;
    if (which == 0) {
        #pragma unroll
        for (int mi = 0; mi < 2; ++mi) {
            int r = r0 + 32 * wm + 16 * mi + gid;
            #pragma unroll
            for (int ni = 0; ni < 8; ++ni) {
                int c = ni * 8 + 2 * qid;
                *(uint32_t*)(g_QPh + (size_t)r * HD + c) =
                    f22h(o[mi][ni][0] * qscale, o[mi][ni][1] * qscale);
                *(uint32_t*)(g_QPh + (size_t)(r + 8) * HD + c) =
                    f22h(o[mi][ni][2] * qscale, o[mi][ni][3] * qscale);
            }
        }
    } else {
        // V: transpose through smem, then fully-coalesced row-major stores
        const int bh = r0 >> 11;
        const size_t base = (size_t)bh * HD * SEQ;
        const int l0 = (r0 & 2047);
        __half* Vt = (__half*)sm;                  // 64 x VT_P halves (reuses Xs)
        __syncthreads();
        #pragma unroll
        for (int mi = 0; mi < 2; ++mi) {
            int l = 32 * wm + 16 * mi + gid;
            #pragma unroll
            for (int ni = 0; ni < 8; ++ni) {
                int c = ni * 8 + 2 * qid;
                Vt[c * VT_P + l]           = __float2half_rn(o[mi][ni][0]);
                Vt[(c + 1) * VT_P + l]     = __float2half_rn(o[mi][ni][1]);
                Vt[c * VT_P + l + 8]       = __float2half_rn(o[mi][ni][2]);
                Vt[(c + 1) * VT_P + l + 8] = __float2half_rn(o[mi][ni][3]);
            }
        }
        __syncthreads();
        #pragma unroll
        for (int p = 0; p < 16; ++p) {
            int d = p * 4 + wm;
            uint2 v = *(const uint2*)(Vt + d * VT_P + lane * 4);
            *(uint2*)(g_VPt + base + (size_t)d * SEQ + l0 + lane * 4) = v;
        }
    }
}

// ---------------------------------------------------------------------------
// Kernel 2: fp16 flash attention, no-max softmax, fp16-accum QK.
// R12 structure (single S buffer) with one reorder: exp2 -> PV -> row sums,
// so the hadd2 tree overlaps the PV mma drain instead of delaying its issue.
// grid (SEQ/128, BH), block 128, dyn smem 73728 B, 2 CTAs/SM.
// ---------------------------------------------------------------------------
__global__ __launch_bounds__(128, 2) void attn_kernel()
{
    extern __shared__ __align__(16) unsigned char smraw[];
    __half* KV = (__half*)smraw;     // 4 stages x (K 64xPH + V 64xPH)

    const int tid  = threadIdx.x;
    const int lane = tid & 31, wm = tid >> 5;      // wm 0..3
    const int gid  = lane >> 2, qid = lane & 3;
    const int bh = blockIdx.y;
    const int q0 = blockIdx.x * 128;

    const uint32_t kv_smem = (uint32_t)__cvta_generic_to_shared(KV);
    const int TILE_H = 64 * PH;
    const int TILE_B = TILE_H * 2;       // 9216 B
    const int NT = SEQ / 64;             // 32

    const __half* Kg0 = g_KPh + (size_t)bh * SEQ * HD;
    const __half* Vg0 = g_VPt + (size_t)bh * HD * SEQ;

    const uint32_t lane_off =
        (uint32_t)((((lane & 7) + ((lane >> 4) << 3)) * PH + ((lane >> 3) & 1) * 8) * 2);

    // prefetch tiles 0, 1, 2 into stages 0, 1, 2
    #pragma unroll
    for (int t = 0; t < 3; ++t) {
        uint32_t base = kv_smem + (uint32_t)(t * 2 * TILE_B);
        #pragma unroll
        for (int i = 0; i < 4; ++i) {
            int g = tid + i * 128;                   // 0..511
            int row = g >> 3, c8 = g & 7;
            uint32_t off = (uint32_t)(row * 144 + c8 * 16);
            cp16(base + off, Kg0 + (size_t)(t * 64 + row) * HD + c8 * 8);
            cp16(base + (uint32_t)TILE_B + off, Vg0 + (size_t)row * SEQ + t * 64 + c8 * 8);
        }
        cp_commit();
    }

    // Q fragments straight from gmem (pre-scaled half)
    uint32_t qf[2][4][4];
    {
        const __half* Qg = g_QPh + (size_t)(bh * SEQ + q0 + 32 * wm + gid) * HD;
        #pragma unroll
        for (int mi = 0; mi < 2; ++mi) {
            const __half* Qm = Qg + (size_t)(16 * mi) * HD;
            #pragma unroll
            for (int kt = 0; kt < 4; ++kt) {
                int c = kt * 16 + 2 * qid;
                qf[mi][kt][0] = *(const uint32_t*)(Qm + c);
                qf[mi][kt][1] = *(const uint32_t*)(Qm + 8 * HD + c);
                qf[mi][kt][2] = *(const uint32_t*)(Qm + c + 8);
                qf[mi][kt][3] = *(const uint32_t*)(Qm + 8 * HD + c + 8);
            }
        }
    }

    float o[2][8][4];
    #pragma unroll
    for (int mi = 0; mi < 2; ++mi)
        #pragma unroll
        for (int ni = 0; ni < 8; ++ni)
            #pragma unroll
            for (int t = 0; t < 4; ++t) o[mi][ni][t] = 0.f;
    float lsum[2][2] = {{0.f, 0.f}, {0.f, 0.f}};

    for (int t = 0; t < NT; ++t) {
        if (t < NT - 2) cp_wait2();
        else if (t == NT - 2) cp_wait1();
        else cp_wait0();
        __syncthreads();

        const int buf = t & 3;
        __half* Ks = KV + buf * 2 * TILE_H;
        __half* Vs = Ks + TILE_H;

        if (t + 3 < NT) {
            const int nb = (t + 3) & 3;
            uint32_t base = kv_smem + (uint32_t)(nb * 2 * TILE_B);
            const __half* Kg = Kg0 + (size_t)(t + 3) * 64 * HD;
            const __half* Vg = Vg0 + (t + 3) * 64;
            #pragma unroll
            for (int i = 0; i < 4; ++i) {
                int g = tid + i * 128;
                int row = g >> 3, c8 = g & 7;
                uint32_t off = (uint32_t)(row * 144 + c8 * 16);
                cp16(base + off, Kg + (size_t)row * HD + c8 * 8);
                cp16(base + (uint32_t)TILE_B + off, Vg + (size_t)row * SEQ + c8 * 8);
            }
            cp_commit();
        }

        // ---- S = Q K^T (fp16 accumulate -> S already packed half2) ----
        uint32_t sacc[2][8][2];
        #pragma unroll
        for (int mi = 0; mi < 2; ++mi)
            #pragma unroll
            for (int ni = 0; ni < 8; ++ni) {
                sacc[mi][ni][0] = 0u;
                sacc[mi][ni][1] = 0u;
            }

        const uint32_t KsS = (uint32_t)__cvta_generic_to_shared(Ks) + lane_off;
        #pragma unroll
        for (int kt = 0; kt < 4; ++kt) {
            #pragma unroll
            for (int nip = 0; nip < 4; ++nip) {
                uint32_t b0, b1, b2, b3;
                ldsm4(b0, b1, b2, b3, KsS + (uint32_t)((nip * 16 * PH + kt * 16) * 2));
                #pragma unroll
                for (int mi = 0; mi < 2; ++mi) {
                    mma16h(sacc[mi][2 * nip][0], sacc[mi][2 * nip][1],
                           qf[mi][kt][0], qf[mi][kt][1], qf[mi][kt][2], qf[mi][kt][3], b0, b1);
                    mma16h(sacc[mi][2 * nip + 1][0], sacc[mi][2 * nip + 1][1],
                           qf[mi][kt][0], qf[mi][kt][1], qf[mi][kt][2], qf[mi][kt][3], b2, b3);
                }
            }
        }

        // ---- P = exp2(S) in place (packed half2, A-fragment layout) ----
        #pragma unroll
        for (int mi = 0; mi < 2; ++mi)
            #pragma unroll
            for (int ni = 0; ni < 8; ++ni) {
                sacc[mi][ni][0] = h2u(h2exp2(u2h(sacc[mi][ni][0])));
                sacc[mi][ni][1] = h2u(h2exp2(u2h(sacc[mi][ni][1])));
            }

        // ---- O += P V (issue immediately; sums follow and overlap drain) ----
        const uint32_t VsS = (uint32_t)__cvta_generic_to_shared(Vs) + lane_off;
        #pragma unroll
        for (int kt = 0; kt < 4; ++kt) {
            #pragma unroll
            for (int nip = 0; nip < 4; ++nip) {
                uint32_t v0, v1, v2, v3;
                ldsm4(v0, v1, v2, v3, VsS + (uint32_t)((nip * 16 * PH + kt * 16) * 2));
                #pragma unroll
                for (int mi = 0; mi < 2; ++mi) {
                    mma16(o[mi][2 * nip][0], o[mi][2 * nip][1],
                          o[mi][2 * nip][2], o[mi][2 * nip][3],
                          sacc[mi][2 * kt][0], sacc[mi][2 * kt][1],
                          sacc[mi][2 * kt + 1][0], sacc[mi][2 * kt + 1][1], v0, v1);
                    mma16(o[mi][2 * nip + 1][0], o[mi][2 * nip + 1][1],
                          o[mi][2 * nip + 1][2], o[mi][2 * nip + 1][3],
                          sacc[mi][2 * kt][0], sacc[mi][2 * kt][1],
                          sacc[mi][2 * kt + 1][0], sacc[mi][2 * kt + 1][1], v2, v3);
                }
            }
        }

        // ---- row-sum partials (overlaps PV drain) ----
        #pragma unroll
        for (int mi = 0; mi < 2; ++mi) {
            __half2 s0t = __hadd2(
                __hadd2(__hadd2(u2h(sacc[mi][0][0]), u2h(sacc[mi][1][0])),
                        __hadd2(u2h(sacc[mi][2][0]), u2h(sacc[mi][3][0]))),
                __hadd2(__hadd2(u2h(sacc[mi][4][0]), u2h(sacc[mi][5][0])),
                        __hadd2(u2h(sacc[mi][6][0]), u2h(sacc[mi][7][0]))));
            __half2 s1t = __hadd2(
                __hadd2(__hadd2(u2h(sacc[mi][0][1]), u2h(sacc[mi][1][1])),
                        __hadd2(u2h(sacc[mi][2][1]), u2h(sacc[mi][3][1]))),
                __hadd2(__hadd2(u2h(sacc[mi][4][1]), u2h(sacc[mi][5][1])),
                        __hadd2(u2h(sacc[mi][6][1]), u2h(sacc[mi][7][1]))));
            float2 s0f = __half22float2(s0t);
            float2 s1f = __half22float2(s1t);
            lsum[mi][0] += s0f.x + s0f.y;
            lsum[mi][1] += s1f.x + s1f.y;
        }
    }

    // epilogue: reduce l across the qid quad, normalize, store half
    const int b = bh >> 3, hh = bh & 7;
    #pragma unroll
    for (int mi = 0; mi < 2; ++mi) {
        float l0 = lsum[mi][0], l1 = lsum[mi][1];
        l0 += __shfl_xor_sync(0xffffffffu, l0, 1);
        l0 += __shfl_xor_sync(0xffffffffu, l0, 2);
        l1 += __shfl_xor_sync(0xffffffffu, l1, 1);
        l1 += __shfl_xor_sync(0xffffffffu, l1, 2);
        const float inv0 = 1.0f / l0;
        const float inv1 = 1.0f / l1;
        const int r = q0 + 32 * wm + 16 * mi + gid;
        #pragma unroll
        for (int ni = 0; ni < 8; ++ni) {
            int c = ni * 8 + 2 * qid;
            *(uint32_t*)(g_AOh + (size_t)(b * SEQ + r) * EMB + hh * HD + c) =
                f22h(o[mi][ni][0] * inv0, o[mi][ni][1] * inv0);
            *(uint32_t*)(g_AOh + (size_t)(b * SEQ + r + 8) * EMB + hh * HD + c) =
                f22h(o[mi][ni][2] * inv1, o[mi][ni][3] * inv1);
        }
    }
}

// ---------------------------------------------------------------------------
// Kernel 3: out = AOh @ Woh^T + bo  (16384 x 512 x 512), fp16 mma.
// tile m128 x n64, block 128, grid (128, 8) = 1024 CTAs, 3 CTAs/SM.
// ---------------------------------------------------------------------------
__global__ __launch_bounds__(128, 3) void out_proj_kernel(
    const float* __restrict__ bo, float* __restrict__ out)
{
    extern __shared__ __align__(16) unsigned char smraw[];
    const int tid  = threadIdx.x;
    const int lane = tid & 31, wm = tid >> 5;
    const int gid  = lane >> 2, qid = lane & 3;
    const int m0 = blockIdx.x * 128;
    const int n0 = blockIdx.y * 64;

    const uint32_t sm0 = (uint32_t)__cvta_generic_to_shared(smraw);
    const int BUF_B = (128 + 64) * 144;   // 27648 B

    auto prefetch = [&](int c) {
        uint32_t base = sm0 + (uint32_t)((c & 1) * BUF_B);
        int k0 = c * 64;
        #pragma unroll
        for (int i = 0; i < 8; ++i) {
            int g = tid + i * 128;
            int row = g >> 3, c8 = g & 7;
            cp16(base + (uint32_t)(row * 144 + c8 * 16),
                 g_AOh + (size_t)(m0 + row) * EMB + k0 + c8 * 8);
        }
        #pragma unroll
        for (int i = 0; i < 4; ++i) {
            int g = tid + i * 128;
            int row = g >> 3, c8 = g & 7;
            cp16(base + (uint32_t)(128 * 144 + row * 144 + c8 * 16),
                 g_Woh + (size_t)(n0 + row) * EMB + k0 + c8 * 8);
        }
        cp_commit();
    };

    prefetch(0);

    float o[2][8][4];
    #pragma unroll
    for (int mi = 0; mi < 2; ++mi)
        #pragma unroll
        for (int ni = 0; ni < 8; ++ni)
            #pragma unroll
            for (int t = 0; t < 4; ++t) o[mi][ni][t] = 0.f;

    const uint32_t laneA = (uint32_t)(((lane & 15) * PH + (lane >> 4) * 8) * 2);
    const uint32_t laneB =
        (uint32_t)((((lane & 7) + ((lane >> 4) << 3)) * PH + ((lane >> 3) & 1) * 8) * 2);

    for (int c = 0; c < 8; ++c) {
        cp_wait0();
        __syncthreads();
        if (c + 1 < 8) prefetch(c + 1);

        uint32_t AsS = sm0 + (uint32_t)((c & 1) * BUF_B) + laneA;
        uint32_t BsS = sm0 + (uint32_t)((c & 1) * BUF_B + 128 * 144) + laneB;

        #pragma unroll
        for (int kt = 0; kt < 4; ++kt) {
            uint32_t a[2][4];
            #pragma unroll
            for (int mi = 0; mi < 2; ++mi)
                ldsm4(a[mi][0], a[mi][1], a[mi][2], a[mi][3],
                      AsS + (uint32_t)((((32 * wm + 16 * mi) * PH) + kt * 16) * 2));
            #pragma unroll
            for (int nip = 0; nip < 4; ++nip) {
                uint32_t b0, b1, b2, b3;
                ldsm4(b0, b1, b2, b3,
                      BsS + (uint32_t)(((nip * 16 * PH) + kt * 16) * 2));
                #pragma unroll
                for (int mi = 0; mi < 2; ++mi) {
                    mma16(o[mi][2 * nip][0], o[mi][2 * nip][1],
                          o[mi][2 * nip][2], o[mi][2 * nip][3],
                          a[mi][0], a[mi][1], a[mi][2], a[mi][3], b0, b1);
                    mma16(o[mi][2 * nip + 1][0], o[mi][2 * nip + 1][1],
                          o[mi][2 * nip + 1][2], o[mi][2 * nip + 1][3],
                          a[mi][0], a[mi][1], a[mi][2], a[mi][3], b2, b3);
                }
            }
        }
    }

    #pragma unroll
    for (int mi = 0; mi < 2; ++mi) {
        int r = m0 + 32 * wm + 16 * mi + gid;
        #pragma unroll
        for (int ni = 0; ni < 8; ++ni) {
            int cc = n0 + ni * 8 + 2 * qid;
            float bb0 = bo[cc], bb1 = bo[cc + 1];
            *(float2*)(out + (size_t)r * EMB + cc) =
                make_float2(o[mi][ni][0] + bb0, o[mi][ni][1] + bb1);
            *(float2*)(out + (size_t)(r + 8) * EMB + cc) =
                make_float2(o[mi][ni][2] + bb0, o[mi][ni][3] + bb1);
        }
    }
}

// ---------------------------------------------------------------------------
extern "C" void kernel_launch(void* const* d_in, const int* in_sizes, int n_in,
                              void* d_out, int out_size)
{
    const float* q  = (const float*)d_in[0];
    const float* k  = (const float*)d_in[1];
    const float* v  = (const float*)d_in[2];
    const float* Wq = (const float*)d_in[3];
    const float* Wk = (const float*)d_in[4];
    const float* Wv = (const float*)d_in[5];
    const float* Wo = (const float*)d_in[6];
    const float* bo = (const float*)d_in[7];
    float* out = (float*)d_out;

    const int proj_smem  = (128 * PITCH + 64 * PITCH) * (int)sizeof(float);   // 52224
    const int attn_smem  = 4 * 2 * 64 * PH * 2;                               // 73728
    const int oproj_smem = 2 * (128 + 64) * 144;                              // 55296

    cudaFuncSetAttribute(proj_kernel, cudaFuncAttributeMaxDynamicSharedMemorySize, proj_smem);
    cudaFuncSetAttribute(attn_kernel, cudaFuncAttributeMaxDynamicSharedMemorySize, attn_smem);
    cudaFuncSetAttribute(out_proj_kernel, cudaFuncAttributeMaxDynamicSharedMemorySize, oproj_smem);

    conv_wo_kernel<<<256, 256>>>(Wo);
    m_fold_kernel<<<16, 256>>>(Wq, Wk);
    proj_kernel<<<dim3(NROWS / 128, 3, 1), 128, proj_smem>>>(q, k, v, Wv);
    attn_kernel<<<dim3(SEQ / 128, BH, 1), 128, attn_smem>>>();
    out_proj_kernel<<<dim3((NB * SEQ) / 128, EMB / 64, 1), 128, oproj_smem>>>(bo, out);
}

// round 15
// speedup vs baseline: 1.4970x; 1.0064x over previous
#include <cuda_runtime.h>
#include <cuda_fp16.h>
#include <cstdint>

// Problem constants
#define NB   8
#define NH   8
#define SEQ  2048
#define HD   64
#define EMB  512
#define BH   (NB * NH)          // 64
#define NROWS (BH * SEQ)        // 131072

#define PITCH 68                // fp32 smem pitch (proj kernel)
#define P4    17
#define PH    72                // half smem pitch (72 halves = 144 B)
#define VT_P  136               // V-transpose staging pitch (halves)

// Scratch (__device__ globals)
static __device__ __align__(256) __half g_QPh[BH * SEQ * HD];  // [bh][l][d], Qm scaled by log2(e)/sqrt(512)
static __device__ __align__(256) __half g_KPh[BH * SEQ * HD];  // [bh][l][d]  (raw key, converted)
static __device__ __align__(256) __half g_VPt[BH * HD * SEQ];  // [bh][d][l]  (transposed)
static __device__ __align__(256) __half g_AOh[NB * SEQ * EMB]; // [b][l][e]
static __device__ __align__(256) __half g_Woh[EMB * EMB];      // Wo as half
static __device__ __align__(256) float  g_Wqk[HD * HD];        // (Wq^T Wk) arranged [n][k]

__device__ __forceinline__ float tf32r(float x) {
    uint32_t u;
    asm("cvt.rna.tf32.f32 %0, %1;" : "=r"(u) : "f"(x));
    return __uint_as_float(u);
}
__device__ __forceinline__ uint32_t f22h(float lo, float hi) {
    __half2 h = __floats2half2_rn(lo, hi);
    return *reinterpret_cast<uint32_t*>(&h);
}
__device__ __forceinline__ uint32_t h2u(__half2 h) {
    return *reinterpret_cast<uint32_t*>(&h);
}
__device__ __forceinline__ __half2 u2h(uint32_t u) {
    return *reinterpret_cast<__half2*>(&u);
}

// tf32 mma (proj only)
__device__ __forceinline__ void mma8(float& c0, float& c1, float& c2, float& c3,
                                     float a0, float a1, float a2, float a3,
                                     float b0, float b1) {
    asm volatile(
        "mma.sync.aligned.m16n8k8.row.col.f32.tf32.tf32.f32 "
        "{%0,%1,%2,%3}, {%4,%5,%6,%7}, {%8,%9}, {%0,%1,%2,%3};\n"
        : "+f"(c0), "+f"(c1), "+f"(c2), "+f"(c3)
        : "r"(__float_as_uint(a0)), "r"(__float_as_uint(a1)),
          "r"(__float_as_uint(a2)), "r"(__float_as_uint(a3)),
          "r"(__float_as_uint(b0)), "r"(__float_as_uint(b1)));
}
// fp16 mma, f32 accum
__device__ __forceinline__ void mma16(float& c0, float& c1, float& c2, float& c3,
                                      uint32_t a0, uint32_t a1, uint32_t a2, uint32_t a3,
                                      uint32_t b0, uint32_t b1) {
    asm volatile(
        "mma.sync.aligned.m16n8k16.row.col.f32.f16.f16.f32 "
        "{%0,%1,%2,%3}, {%4,%5,%6,%7}, {%8,%9}, {%0,%1,%2,%3};\n"
        : "+f"(c0), "+f"(c1), "+f"(c2), "+f"(c3)
        : "r"(a0), "r"(a1), "r"(a2), "r"(a3), "r"(b0), "r"(b1));
}
// fp16 mma, f16 accum (QK path: S emerges pre-packed as half2)
__device__ __forceinline__ void mma16h(uint32_t& c0, uint32_t& c1,
                                       uint32_t a0, uint32_t a1, uint32_t a2, uint32_t a3,
                                       uint32_t b0, uint32_t b1) {
    asm volatile(
        "mma.sync.aligned.m16n8k16.row.col.f16.f16.f16.f16 "
        "{%0,%1}, {%2,%3,%4,%5}, {%6,%7}, {%0,%1};\n"
        : "+r"(c0), "+r"(c1)
        : "r"(a0), "r"(a1), "r"(a2), "r"(a3), "r"(b0), "r"(b1));
}

__device__ __forceinline__ void ldsm4(uint32_t& r0, uint32_t& r1, uint32_t& r2, uint32_t& r3,
                                      uint32_t a) {
    asm volatile("ldmatrix.sync.aligned.m8n8.x4.shared.b16 {%0,%1,%2,%3}, [%4];"
                 : "=r"(r0), "=r"(r1), "=r"(r2), "=r"(r3) : "r"(a));
}

__device__ __forceinline__ void cp16(uint32_t dst, const void* src) {
    asm volatile("cp.async.cg.shared.global [%0], [%1], 16;" :: "r"(dst), "l"(src));
}
__device__ __forceinline__ void cp_commit() { asm volatile("cp.async.commit_group;"); }
__device__ __forceinline__ void cp_wait0()  { asm volatile("cp.async.wait_group 0;"); }
__device__ __forceinline__ void cp_wait1()  { asm volatile("cp.async.wait_group 1;"); }
__device__ __forceinline__ void cp_wait2()  { asm volatile("cp.async.wait_group 2;"); }

// ---------------------------------------------------------------------------
// Kernel 0: merged setup — Wo fp32->half (blocks 0..255) and
// M_eff[n][k] = (Wq^T Wk)[k][n] fold (blocks 256..271). block 256.
// ---------------------------------------------------------------------------
__global__ __launch_bounds__(256) void setup_kernel(
    const float* __restrict__ Wo,
    const float* __restrict__ Wq, const float* __restrict__ Wk)
{
    if (blockIdx.x < 256) {
        int i = blockIdx.x * 256 + threadIdx.x;        // 65536 float4s
        float4 w = ((const float4*)Wo)[i];
        uint2 p;
        p.x = f22h(w.x, w.y);
        p.y = f22h(w.z, w.w);
        ((uint2*)g_Woh)[i] = p;
    } else {
        int idx = (blockIdx.x - 256) * 256 + threadIdx.x;   // 0..4095
        int n = idx >> 6, k = idx & 63;
        float s = 0.f;
        #pragma unroll 8
        for (int t = 0; t < 64; ++t)
            s += Wq[t * 64 + k] * Wk[t * 64 + n];
        g_Wqk[idx] = s;
    }
}

// ---------------------------------------------------------------------------
// Kernel 1: projections.
//  which 0: Qm = Xq @ (Wq^T Wk)  (tf32 mma, scaled)  -> g_QPh
//  which 1: pure convert raw key -> g_KPh
//  which 2: V proj (tf32 mma) -> g_VPt via coalesced smem transpose
// grid (NROWS/128, 3), block 128
// ---------------------------------------------------------------------------
__global__ __launch_bounds__(128) void proj_kernel(
    const float* __restrict__ Qin, const float* __restrict__ Kin,
    const float* __restrict__ Vin, const float* __restrict__ Wv)
{
    extern __shared__ float sm[];
    float* Xs = sm;                 // 128 x PITCH
    float* Ws = sm + 128 * PITCH;   // 64 x PITCH

    const int tid  = threadIdx.x;
    const int which = blockIdx.y;
    const int r0 = blockIdx.x * 128;

    if (which == 1) {
        const float4* X4 = (const float4*)(Kin + (size_t)r0 * HD);
        uint2* O2 = (uint2*)(g_KPh + (size_t)r0 * HD);
        #pragma unroll
        for (int i = 0; i < 16; ++i) {
            int g = tid + i * 128;
            float4 v = X4[g];
            uint2 p;
            p.x = f22h(v.x, v.y);
            p.y = f22h(v.z, v.w);
            O2[g] = p;
        }
        return;
    }

    const int lane = tid & 31, wm = tid >> 5;
    const int gid  = lane >> 2, qid = lane & 3;
    const float* W = (which == 0) ? g_Wqk : Wv;

    const float4* W4 = (const float4*)W;
    #pragma unroll
    for (int i = 0; i < 8; ++i) {
        int g = tid + i * 128;
        float4 w = W4[g];
        w.x = tf32r(w.x); w.y = tf32r(w.y); w.z = tf32r(w.z); w.w = tf32r(w.w);
        ((float4*)Ws)[(g >> 4) * P4 + (g & 15)] = w;
    }
    if (which == 0) {
        const float4* X4 = (const float4*)(Qin + (size_t)r0 * HD);
        #pragma unroll
        for (int i = 0; i < 16; ++i) {
            int g = tid + i * 128;
            float4 v = X4[g];
            v.x = tf32r(v.x); v.y = tf32r(v.y); v.z = tf32r(v.z); v.w = tf32r(v.w);
            ((float4*)Xs)[(g >> 4) * P4 + (g & 15)] = v;
        }
    } else {
        const int bh = r0 >> 11, l0 = r0 & 2047;
        const int b = bh >> 3, h = bh & 7;
        const float* base = Vin + ((size_t)(b * SEQ + l0)) * EMB + h * HD;
        #pragma unroll
        for (int i = 0; i < 16; ++i) {
            int g = tid + i * 128;
            int r = g >> 4, c4 = g & 15;
            float4 v = *(const float4*)(base + (size_t)r * EMB + c4 * 4);
            v.x = tf32r(v.x); v.y = tf32r(v.y); v.z = tf32r(v.z); v.w = tf32r(v.w);
            ((float4*)Xs)[r * P4 + c4] = v;
        }
    }
    __syncthreads();

    float o[2][8][4];
    #pragma unroll
    for (int mi = 0; mi < 2; ++mi)
        #pragma unroll
        for (int ni = 0; ni < 8; ++ni)
            #pragma unroll
            for (int t = 0; t < 4; ++t) o[mi][ni][t] = 0.f;

    #pragma unroll
    for (int ks = 0; ks < 8; ++ks) {
        float a[2][4];
        #pragma unroll
        for (int mi = 0; mi < 2; ++mi) {
            int r = 32 * wm + 16 * mi + gid;
            int c = ks * 8 + qid;
            a[mi][0] = Xs[r * PITCH + c];
            a[mi][1] = Xs[(r + 8) * PITCH + c];
            a[mi][2] = Xs[r * PITCH + c + 4];
            a[mi][3] = Xs[(r + 8) * PITCH + c + 4];
        }
        #pragma unroll
        for (int ni = 0; ni < 8; ++ni) {
            float b0 = Ws[(ni * 8 + gid) * PITCH + ks * 8 + qid];
            float b1 = Ws[(ni * 8 + gid) * PITCH + ks * 8 + qid + 4];
            #pragma unroll
            for (int mi = 0; mi < 2; ++mi)
                mma8(o[mi][ni][0], o[mi][ni][1], o[mi][ni][2], o[mi][ni][3],
                     a[mi][0], a[mi][1], a[mi][2], a[mi][3], b0, b1);
        }
    }

    // 1/sqrt(512) * log2(e): softmax computed in base-2
    const float qscale = 0.06375863286367196f;
    if (which == 0) {
        #pragma unroll
        for (int mi = 0; mi < 2; ++mi) {
            int r = r0 + 32 * wm + 16 * mi + gid;
            #pragma unroll
            for (int ni = 0; ni < 8; ++ni) {
                int c = ni * 8 + 2 * qid;
                *(uint32_t*)(g_QPh + (size_t)r * HD + c) =
                    f22h(o[mi][ni][0] * qscale, o[mi][ni][1] * qscale);
                *(uint32_t*)(g_QPh + (size_t)(r + 8) * HD + c) =
                    f22h(o[mi][ni][2] * qscale, o[mi][ni][3] * qscale);
            }
        }
    } else {
        // V: transpose through smem, then fully-coalesced row-major stores
        const int bh = r0 >> 11;
        const size_t base = (size_t)bh * HD * SEQ;
        const int l0 = (r0 & 2047);
        __half* Vt = (__half*)sm;                  // 64 x VT_P halves (reuses Xs)
        __syncthreads();
        #pragma unroll
        for (int mi = 0; mi < 2; ++mi) {
            int l = 32 * wm + 16 * mi + gid;
            #pragma unroll
            for (int ni = 0; ni < 8; ++ni) {
                int c = ni * 8 + 2 * qid;
                Vt[c * VT_P + l]           = __float2half_rn(o[mi][ni][0]);
                Vt[(c + 1) * VT_P + l]     = __float2half_rn(o[mi][ni][1]);
                Vt[c * VT_P + l + 8]       = __float2half_rn(o[mi][ni][2]);
                Vt[(c + 1) * VT_P + l + 8] = __float2half_rn(o[mi][ni][3]);
            }
        }
        __syncthreads();
        #pragma unroll
        for (int p = 0; p < 16; ++p) {
            int d = p * 4 + wm;
            uint2 v = *(const uint2*)(Vt + d * VT_P + lane * 4);
            *(uint2*)(g_VPt + base + (size_t)d * SEQ + l0 + lane * 4) = v;
        }
    }
}

// ---------------------------------------------------------------------------
// Kernel 2: fp16 flash attention, no-max softmax, fp16-accum QK.
// QK loop interchanged (nip-outer): each S column-pair finishes early and its
// exp2 overlaps the next column's mma issue. Register-neutral.
// grid (SEQ/128, BH), block 128, dyn smem 73728 B, 2 CTAs/SM.
// ---------------------------------------------------------------------------
__global__ __launch_bounds__(128, 2) void attn_kernel()
{
    extern __shared__ __align__(16) unsigned char smraw[];
    __half* KV = (__half*)smraw;     // 4 stages x (K 64xPH + V 64xPH)

    const int tid  = threadIdx.x;
    const int lane = tid & 31, wm = tid >> 5;      // wm 0..3
    const int gid  = lane >> 2, qid = lane & 3;
    const int bh = blockIdx.y;
    const int q0 = blockIdx.x * 128;

    const uint32_t kv_smem = (uint32_t)__cvta_generic_to_shared(KV);
    const int TILE_H = 64 * PH;
    const int TILE_B = TILE_H * 2;       // 9216 B
    const int NT = SEQ / 64;             // 32

    const __half* Kg0 = g_KPh + (size_t)bh * SEQ * HD;
    const __half* Vg0 = g_VPt + (size_t)bh * HD * SEQ;

    const uint32_t lane_off =
        (uint32_t)((((lane & 7) + ((lane >> 4) << 3)) * PH + ((lane >> 3) & 1) * 8) * 2);

    // prefetch tiles 0, 1, 2 into stages 0, 1, 2
    #pragma unroll
    for (int t = 0; t < 3; ++t) {
        uint32_t base = kv_smem + (uint32_t)(t * 2 * TILE_B);
        #pragma unroll
        for (int i = 0; i < 4; ++i) {
            int g = tid + i * 128;                   // 0..511
            int row = g >> 3, c8 = g & 7;
            uint32_t off = (uint32_t)(row * 144 + c8 * 16);
            cp16(base + off, Kg0 + (size_t)(t * 64 + row) * HD + c8 * 8);
            cp16(base + (uint32_t)TILE_B + off, Vg0 + (size_t)row * SEQ + t * 64 + c8 * 8);
        }
        cp_commit();
    }

    // Q fragments straight from gmem (pre-scaled half)
    uint32_t qf[2][4][4];
    {
        const __half* Qg = g_QPh + (size_t)(bh * SEQ + q0 + 32 * wm + gid) * HD;
        #pragma unroll
        for (int mi = 0; mi < 2; ++mi) {
            const __half* Qm = Qg + (size_t)(16 * mi) * HD;
            #pragma unroll
            for (int kt = 0; kt < 4; ++kt) {
                int c = kt * 16 + 2 * qid;
                qf[mi][kt][0] = *(const uint32_t*)(Qm + c);
                qf[mi][kt][1] = *(const uint32_t*)(Qm + 8 * HD + c);
                qf[mi][kt][2] = *(const uint32_t*)(Qm + c + 8);
                qf[mi][kt][3] = *(const uint32_t*)(Qm + 8 * HD + c + 8);
            }
        }
    }

    float o[2][8][4];
    #pragma unroll
    for (int mi = 0; mi < 2; ++mi)
        #pragma unroll
        for (int ni = 0; ni < 8; ++ni)
            #pragma unroll
            for (int t = 0; t < 4; ++t) o[mi][ni][t] = 0.f;
    float lsum[2][2] = {{0.f, 0.f}, {0.f, 0.f}};

    for (int t = 0; t < NT; ++t) {
        if (t < NT - 2) cp_wait2();
        else if (t == NT - 2) cp_wait1();
        else cp_wait0();
        __syncthreads();

        const int buf = t & 3;
        __half* Ks = KV + buf * 2 * TILE_H;
        __half* Vs = Ks + TILE_H;

        if (t + 3 < NT) {
            const int nb = (t + 3) & 3;
            uint32_t base = kv_smem + (uint32_t)(nb * 2 * TILE_B);
            const __half* Kg = Kg0 + (size_t)(t + 3) * 64 * HD;
            const __half* Vg = Vg0 + (t + 3) * 64;
            #pragma unroll
            for (int i = 0; i < 4; ++i) {
                int g = tid + i * 128;
                int row = g >> 3, c8 = g & 7;
                uint32_t off = (uint32_t)(row * 144 + c8 * 16);
                cp16(base + off, Kg + (size_t)row * HD + c8 * 8);
                cp16(base + (uint32_t)TILE_B + off, Vg + (size_t)row * SEQ + c8 * 8);
            }
            cp_commit();
        }

        // ---- S = Q K^T, nip-outer; exp2 fused per column pair ----
        uint32_t sacc[2][8][2];
        const uint32_t KsS = (uint32_t)__cvta_generic_to_shared(Ks) + lane_off;
        #pragma unroll
        for (int nip = 0; nip < 4; ++nip) {
            #pragma unroll
            for (int mi = 0; mi < 2; ++mi) {
                sacc[mi][2 * nip][0] = 0u;     sacc[mi][2 * nip][1] = 0u;
                sacc[mi][2 * nip + 1][0] = 0u; sacc[mi][2 * nip + 1][1] = 0u;
            }
            #pragma unroll
            for (int kt = 0; kt < 4; ++kt) {
                uint32_t b0, b1, b2, b3;
                ldsm4(b0, b1, b2, b3, KsS + (uint32_t)((nip * 16 * PH + kt * 16) * 2));
                #pragma unroll
                for (int mi = 0; mi < 2; ++mi) {
                    mma16h(sacc[mi][2 * nip][0], sacc[mi][2 * nip][1],
                           qf[mi][kt][0], qf[mi][kt][1], qf[mi][kt][2], qf[mi][kt][3], b0, b1);
                    mma16h(sacc[mi][2 * nip + 1][0], sacc[mi][2 * nip + 1][1],
                           qf[mi][kt][0], qf[mi][kt][1], qf[mi][kt][2], qf[mi][kt][3], b2, b3);
                }
            }
            // exp2 of this column pair overlaps the next nip's mma issue
            #pragma unroll
            for (int mi = 0; mi < 2; ++mi) {
                sacc[mi][2 * nip][0]     = h2u(h2exp2(u2h(sacc[mi][2 * nip][0])));
                sacc[mi][2 * nip][1]     = h2u(h2exp2(u2h(sacc[mi][2 * nip][1])));
                sacc[mi][2 * nip + 1][0] = h2u(h2exp2(u2h(sacc[mi][2 * nip + 1][0])));
                sacc[mi][2 * nip + 1][1] = h2u(h2exp2(u2h(sacc[mi][2 * nip + 1][1])));
            }
        }

        // ---- O += P V (P in A-fragment layout) ----
        const uint32_t VsS = (uint32_t)__cvta_generic_to_shared(Vs) + lane_off;
        #pragma unroll
        for (int kt = 0; kt < 4; ++kt) {
            #pragma unroll
            for (int nip = 0; nip < 4; ++nip) {
                uint32_t v0, v1, v2, v3;
                ldsm4(v0, v1, v2, v3, VsS + (uint32_t)((nip * 16 * PH + kt * 16) * 2));
                #pragma unroll
                for (int mi = 0; mi < 2; ++mi) {
                    mma16(o[mi][2 * nip][0], o[mi][2 * nip][1],
                          o[mi][2 * nip][2], o[mi][2 * nip][3],
                          sacc[mi][2 * kt][0], sacc[mi][2 * kt][1],
                          sacc[mi][2 * kt + 1][0], sacc[mi][2 * kt + 1][1], v0, v1);
                    mma16(o[mi][2 * nip + 1][0], o[mi][2 * nip + 1][1],
                          o[mi][2 * nip + 1][2], o[mi][2 * nip + 1][3],
                          sacc[mi][2 * kt][0], sacc[mi][2 * kt][1],
                          sacc[mi][2 * kt + 1][0], sacc[mi][2 * kt + 1][1], v2, v3);
                }
            }
        }

        // ---- row-sum partials (overlaps PV drain) ----
        #pragma unroll
        for (int mi = 0; mi < 2; ++mi) {
            __half2 s0t = __hadd2(
                __hadd2(__hadd2(u2h(sacc[mi][0][0]), u2h(sacc[mi][1][0])),
                        __hadd2(u2h(sacc[mi][2][0]), u2h(sacc[mi][3][0]))),
                __hadd2(__hadd2(u2h(sacc[mi][4][0]), u2h(sacc[mi][5][0])),
                        __hadd2(u2h(sacc[mi][6][0]), u2h(sacc[mi][7][0]))));
            __half2 s1t = __hadd2(
                __hadd2(__hadd2(u2h(sacc[mi][0][1]), u2h(sacc[mi][1][1])),
                        __hadd2(u2h(sacc[mi][2][1]), u2h(sacc[mi][3][1]))),
                __hadd2(__hadd2(u2h(sacc[mi][4][1]), u2h(sacc[mi][5][1])),
                        __hadd2(u2h(sacc[mi][6][1]), u2h(sacc[mi][7][1]))));
            float2 s0f = __half22float2(s0t);
            float2 s1f = __half22float2(s1t);
            lsum[mi][0] += s0f.x + s0f.y;
            lsum[mi][1] += s1f.x + s1f.y;
        }
    }

    // epilogue: reduce l across the qid quad, normalize, store half
    const int b = bh >> 3, hh = bh & 7;
    #pragma unroll
    for (int mi = 0; mi < 2; ++mi) {
        float l0 = lsum[mi][0], l1 = lsum[mi][1];
        l0 += __shfl_xor_sync(0xffffffffu, l0, 1);
        l0 += __shfl_xor_sync(0xffffffffu, l0, 2);
        l1 += __shfl_xor_sync(0xffffffffu, l1, 1);
        l1 += __shfl_xor_sync(0xffffffffu, l1, 2);
        const float inv0 = 1.0f / l0;
        const float inv1 = 1.0f / l1;
        const int r = q0 + 32 * wm + 16 * mi + gid;
        #pragma unroll
        for (int ni = 0; ni < 8; ++ni) {
            int c = ni * 8 + 2 * qid;
            *(uint32_t*)(g_AOh + (size_t)(b * SEQ + r) * EMB + hh * HD + c) =
                f22h(o[mi][ni][0] * inv0, o[mi][ni][1] * inv0);
            *(uint32_t*)(g_AOh + (size_t)(b * SEQ + r + 8) * EMB + hh * HD + c) =
                f22h(o[mi][ni][2] * inv1, o[mi][ni][3] * inv1);
        }
    }
}

// ---------------------------------------------------------------------------
// Kernel 3: out = AOh @ Woh^T + bo  (16384 x 512 x 512), fp16 mma.
// tile m128 x n64, block 128, grid (128, 8) = 1024 CTAs, 3 CTAs/SM.
// ---------------------------------------------------------------------------
__global__ __launch_bounds__(128, 3) void out_proj_kernel(
    const float* __restrict__ bo, float* __restrict__ out)
{
    extern __shared__ __align__(16) unsigned char smraw[];
    const int tid  = threadIdx.x;
    const int lane = tid & 31, wm = tid >> 5;
    const int gid  = lane >> 2, qid = lane & 3;
    const int m0 = blockIdx.x * 128;
    const int n0 = blockIdx.y * 64;

    const uint32_t sm0 = (uint32_t)__cvta_generic_to_shared(smraw);
    const int BUF_B = (128 + 64) * 144;   // 27648 B

    auto prefetch = [&](int c) {
        uint32_t base = sm0 + (uint32_t)((c & 1) * BUF_B);
        int k0 = c * 64;
        #pragma unroll
        for (int i = 0; i < 8; ++i) {
            int g = tid + i * 128;
            int row = g >> 3, c8 = g & 7;
            cp16(base + (uint32_t)(row * 144 + c8 * 16),
                 g_AOh + (size_t)(m0 + row) * EMB + k0 + c8 * 8);
        }
        #pragma unroll
        for (int i = 0; i < 4; ++i) {
            int g = tid + i * 128;
            int row = g >> 3, c8 = g & 7;
            cp16(base + (uint32_t)(128 * 144 + row * 144 + c8 * 16),
                 g_Woh + (size_t)(n0 + row) * EMB + k0 + c8 * 8);
        }
        cp_commit();
    };

    prefetch(0);

    float o[2][8][4];
    #pragma unroll
    for (int mi = 0; mi < 2; ++mi)
        #pragma unroll
        for (int ni = 0; ni < 8; ++ni)
            #pragma unroll
            for (int t = 0; t < 4; ++t) o[mi][ni][t] = 0.f;

    const uint32_t laneA = (uint32_t)(((lane & 15) * PH + (lane >> 4) * 8) * 2);
    const uint32_t laneB =
        (uint32_t)((((lane & 7) + ((lane >> 4) << 3)) * PH + ((lane >> 3) & 1) * 8) * 2);

    for (int c = 0; c < 8; ++c) {
        cp_wait0();
        __syncthreads();
        if (c + 1 < 8) prefetch(c + 1);

        uint32_t AsS = sm0 + (uint32_t)((c & 1) * BUF_B) + laneA;
        uint32_t BsS = sm0 + (uint32_t)((c & 1) * BUF_B + 128 * 144) + laneB;

        #pragma unroll
        for (int kt = 0; kt < 4; ++kt) {
            uint32_t a[2][4];
            #pragma unroll
            for (int mi = 0; mi < 2; ++mi)
                ldsm4(a[mi][0], a[mi][1], a[mi][2], a[mi][3],
                      AsS + (uint32_t)((((32 * wm + 16 * mi) * PH) + kt * 16) * 2));
            #pragma unroll
            for (int nip = 0; nip < 4; ++nip) {
                uint32_t b0, b1, b2, b3;
                ldsm4(b0, b1, b2, b3,
                      BsS + (uint32_t)(((nip * 16 * PH) + kt * 16) * 2));
                #pragma unroll
                for (int mi = 0; mi < 2; ++mi) {
                    mma16(o[mi][2 * nip][0], o[mi][2 * nip][1],
                          o[mi][2 * nip][2], o[mi][2 * nip][3],
                          a[mi][0], a[mi][1], a[mi][2], a[mi][3], b0, b1);
                    mma16(o[mi][2 * nip + 1][0], o[mi][2 * nip + 1][1],
                          o[mi][2 * nip + 1][2], o[mi][2 * nip + 1][3],
                          a[mi][0], a[mi][1], a[mi][2], a[mi][3], b2, b3);
                }
            }
        }
    }

    #pragma unroll
    for (int mi = 0; mi < 2; ++mi) {
        int r = m0 + 32 * wm + 16 * mi + gid;
        #pragma unroll
        for (int ni = 0; ni < 8; ++ni) {
            int cc = n0 + ni * 8 + 2 * qid;
            float bb0 = bo[cc], bb1 = bo[cc + 1];
            *(float2*)(out + (size_t)r * EMB + cc) =
                make_float2(o[mi][ni][0] + bb0, o[mi][ni][1] + bb1);
            *(float2*)(out + (size_t)(r + 8) * EMB + cc) =
                make_float2(o[mi][ni][2] + bb0, o[mi][ni][3] + bb1);
        }
    }
}

// ---------------------------------------------------------------------------
extern "C" void kernel_launch(void* const* d_in, const int* in_sizes, int n_in,
                              void* d_out, int out_size)
{
    const float* q  = (const float*)d_in[0];
    const float* k  = (const float*)d_in[1];
    const float* v  = (const float*)d_in[2];
    const float* Wq = (const float*)d_in[3];
    const float* Wk = (const float*)d_in[4];
    const float* Wv = (const float*)d_in[5];
    const float* Wo = (const float*)d_in[6];
    const float* bo = (const float*)d_in[7];
    float* out = (float*)d_out;

    const int proj_smem  = (128 * PITCH + 64 * PITCH) * (int)sizeof(float);   // 52224
    const int attn_smem  = 4 * 2 * 64 * PH * 2;                               // 73728
    const int oproj_smem = 2 * (128 + 64) * 144;                              // 55296

    cudaFuncSetAttribute(proj_kernel, cudaFuncAttributeMaxDynamicSharedMemorySize, proj_smem);
    cudaFuncSetAttribute(attn_kernel, cudaFuncAttributeMaxDynamicSharedMemorySize, attn_smem);
    cudaFuncSetAttribute(out_proj_kernel, cudaFuncAttributeMaxDynamicSharedMemorySize, oproj_smem);

    setup_kernel<<<272, 256>>>(Wo, Wq, Wk);
    proj_kernel<<<dim3(NROWS / 128, 3, 1), 128, proj_smem>>>(q, k, v, Wv);
    attn_kernel<<<dim3(SEQ / 128, BH, 1), 128, attn_smem>>>();
    out_proj_kernel<<<dim3((NB * SEQ) / 128, EMB / 64, 1), 128, oproj_smem>>>(bo, out);
}

// round 16
// speedup vs baseline: 1.5446x; 1.0318x over previous
#include <cuda_runtime.h>
#include <cuda_fp16.h>
#include <cstdint>

// Problem constants
#define NB   8
#define NH   8
#define SEQ  2048
#define HD   64
#define EMB  512
#define BH   (NB * NH)          // 64
#define NROWS (BH * SEQ)        // 131072

#define PH    72                // half smem pitch (72 halves = 144 B)
#define VT_P  136               // V-transpose staging pitch (halves)
#define STAGES 5                // attn cp.async ring depth

// Scratch (__device__ globals)
static __device__ __align__(256) __half g_QPh[BH * SEQ * HD];  // [bh][l][d], Qm scaled by log2(e)/sqrt(512)
static __device__ __align__(256) __half g_KPh[BH * SEQ * HD];  // [bh][l][d]  (raw key, converted)
static __device__ __align__(256) __half g_VPt[BH * HD * SEQ];  // [bh][d][l]  (transposed)
static __device__ __align__(256) __half g_AOh[NB * SEQ * EMB]; // [b][l][e]
static __device__ __align__(256) __half g_Woh[EMB * EMB];      // Wo as half
static __device__ __align__(256) float  g_Wqk[HD * HD];        // (Wq^T Wk) arranged [n][k]

__device__ __forceinline__ uint32_t f22h(float lo, float hi) {
    __half2 h = __floats2half2_rn(lo, hi);
    return *reinterpret_cast<uint32_t*>(&h);
}
__device__ __forceinline__ uint32_t h2u(__half2 h) {
    return *reinterpret_cast<uint32_t*>(&h);
}
__device__ __forceinline__ __half2 u2h(uint32_t u) {
    return *reinterpret_cast<__half2*>(&u);
}

// fp16 mma, f32 accum
__device__ __forceinline__ void mma16(float& c0, float& c1, float& c2, float& c3,
                                      uint32_t a0, uint32_t a1, uint32_t a2, uint32_t a3,
                                      uint32_t b0, uint32_t b1) {
    asm volatile(
        "mma.sync.aligned.m16n8k16.row.col.f32.f16.f16.f32 "
        "{%0,%1,%2,%3}, {%4,%5,%6,%7}, {%8,%9}, {%0,%1,%2,%3};\n"
        : "+f"(c0), "+f"(c1), "+f"(c2), "+f"(c3)
        : "r"(a0), "r"(a1), "r"(a2), "r"(a3), "r"(b0), "r"(b1));
}
// fp16 mma, f16 accum (QK path: S emerges pre-packed as half2)
__device__ __forceinline__ void mma16h(uint32_t& c0, uint32_t& c1,
                                       uint32_t a0, uint32_t a1, uint32_t a2, uint32_t a3,
                                       uint32_t b0, uint32_t b1) {
    asm volatile(
        "mma.sync.aligned.m16n8k16.row.col.f16.f16.f16.f16 "
        "{%0,%1}, {%2,%3,%4,%5}, {%6,%7}, {%0,%1};\n"
        : "+r"(c0), "+r"(c1)
        : "r"(a0), "r"(a1), "r"(a2), "r"(a3), "r"(b0), "r"(b1));
}

__device__ __forceinline__ void ldsm4(uint32_t& r0, uint32_t& r1, uint32_t& r2, uint32_t& r3,
                                      uint32_t a) {
    asm volatile("ldmatrix.sync.aligned.m8n8.x4.shared.b16 {%0,%1,%2,%3}, [%4];"
                 : "=r"(r0), "=r"(r1), "=r"(r2), "=r"(r3) : "r"(a));
}

__device__ __forceinline__ void cp16(uint32_t dst, const void* src) {
    asm volatile("cp.async.cg.shared.global [%0], [%1], 16;" :: "r"(dst), "l"(src));
}
__device__ __forceinline__ void cp_commit() { asm volatile("cp.async.commit_group;"); }
__device__ __forceinline__ void cp_wait0()  { asm volatile("cp.async.wait_group 0;"); }
__device__ __forceinline__ void cp_wait1()  { asm volatile("cp.async.wait_group 1;"); }
__device__ __forceinline__ void cp_wait2()  { asm volatile("cp.async.wait_group 2;"); }
__device__ __forceinline__ void cp_wait3()  { asm volatile("cp.async.wait_group 3;"); }

// ---------------------------------------------------------------------------
// Kernel 0: merged setup — Wo fp32->half (blocks 0..255) and
// M_eff[n][k] = (Wq^T Wk)[k][n] fold (blocks 256..271). block 256.
// ---------------------------------------------------------------------------
__global__ __launch_bounds__(256) void setup_kernel(
    const float* __restrict__ Wo,
    const float* __restrict__ Wq, const float* __restrict__ Wk)
{
    if (blockIdx.x < 256) {
        int i = blockIdx.x * 256 + threadIdx.x;        // 65536 float4s
        float4 w = ((const float4*)Wo)[i];
        uint2 p;
        p.x = f22h(w.x, w.y);
        p.y = f22h(w.z, w.w);
        ((uint2*)g_Woh)[i] = p;
    } else {
        int idx = (blockIdx.x - 256) * 256 + threadIdx.x;   // 0..4095
        int n = idx >> 6, k = idx & 63;
        float s = 0.f;
        #pragma unroll 8
        for (int t = 0; t < 64; ++t)
            s += Wq[t * 64 + k] * Wk[t * 64 + n];
        g_Wqk[idx] = s;
    }
}

// ---------------------------------------------------------------------------
// Kernel 1: projections, fp16 mma (X and W staged as half; smem 27.6 KB
// -> up to 8 CTAs/SM for latency hiding).
//  which 0: Qm = Xq @ (Wq^T Wk)^T-form  -> g_QPh (scaled)
//  which 1: pure convert raw key -> g_KPh
//  which 2: V proj -> g_VPt via coalesced smem transpose
// grid (NROWS/128, 3), block 128
// ---------------------------------------------------------------------------
__global__ __launch_bounds__(128) void proj_kernel(
    const float* __restrict__ Qin, const float* __restrict__ Kin,
    const float* __restrict__ Vin, const float* __restrict__ Wv)
{
    extern __shared__ __align__(16) unsigned char smraw[];
    __half* Xs = (__half*)smraw;                     // 128 x PH
    __half* Ws = (__half*)(smraw + 128 * PH * 2);    // 64 x PH  (Ws[n][k])

    const int tid  = threadIdx.x;
    const int which = blockIdx.y;
    const int r0 = blockIdx.x * 128;

    if (which == 1) {
        const float4* X4 = (const float4*)(Kin + (size_t)r0 * HD);
        uint2* O2 = (uint2*)(g_KPh + (size_t)r0 * HD);
        #pragma unroll
        for (int i = 0; i < 16; ++i) {
            int g = tid + i * 128;
            float4 v = X4[g];
            uint2 p;
            p.x = f22h(v.x, v.y);
            p.y = f22h(v.z, v.w);
            O2[g] = p;
        }
        return;
    }

    const int lane = tid & 31, wm = tid >> 5;
    const int gid  = lane >> 2, qid = lane & 3;
    const float* W = (which == 0) ? g_Wqk : Wv;

    // stage W (64x64) as half
    const float4* W4 = (const float4*)W;
    #pragma unroll
    for (int i = 0; i < 8; ++i) {
        int g = tid + i * 128;                       // 0..1023 float4s
        int row = g >> 4, c4 = g & 15;               // 16 float4 per row
        float4 w = W4[g];
        uint2 p;
        p.x = f22h(w.x, w.y);
        p.y = f22h(w.z, w.w);
        *(uint2*)(Ws + row * PH + c4 * 4) = p;
    }
    // stage X (128x64) as half
    if (which == 0) {
        const float4* X4 = (const float4*)(Qin + (size_t)r0 * HD);
        #pragma unroll
        for (int i = 0; i < 16; ++i) {
            int g = tid + i * 128;                   // 0..2047
            int row = g >> 4, c4 = g & 15;
            float4 v = X4[g];
            uint2 p;
            p.x = f22h(v.x, v.y);
            p.y = f22h(v.z, v.w);
            *(uint2*)(Xs + row * PH + c4 * 4) = p;
        }
    } else {
        const int bh = r0 >> 11, l0 = r0 & 2047;
        const int b = bh >> 3, h = bh & 7;
        const float* base = Vin + ((size_t)(b * SEQ + l0)) * EMB + h * HD;
        #pragma unroll
        for (int i = 0; i < 16; ++i) {
            int g = tid + i * 128;
            int row = g >> 4, c4 = g & 15;
            float4 v = *(const float4*)(base + (size_t)row * EMB + c4 * 4);
            uint2 p;
            p.x = f22h(v.x, v.y);
            p.y = f22h(v.z, v.w);
            *(uint2*)(Xs + row * PH + c4 * 4) = p;
        }
    }
    __syncthreads();

    const uint32_t laneA = (uint32_t)(((lane & 15) * PH + (lane >> 4) * 8) * 2);
    const uint32_t laneB =
        (uint32_t)((((lane & 7) + ((lane >> 4) << 3)) * PH + ((lane >> 3) & 1) * 8) * 2);
    const uint32_t XsS = (uint32_t)__cvta_generic_to_shared(Xs) + laneA;
    const uint32_t WsS = (uint32_t)__cvta_generic_to_shared(Ws) + laneB;

    float o[2][8][4];
    #pragma unroll
    for (int mi = 0; mi < 2; ++mi)
        #pragma unroll
        for (int ni = 0; ni < 8; ++ni)
            #pragma unroll
            for (int t = 0; t < 4; ++t) o[mi][ni][t] = 0.f;

    #pragma unroll
    for (int kt = 0; kt < 4; ++kt) {
        uint32_t a[2][4];
        #pragma unroll
        for (int mi = 0; mi < 2; ++mi)
            ldsm4(a[mi][0], a[mi][1], a[mi][2], a[mi][3],
                  XsS + (uint32_t)((((32 * wm + 16 * mi) * PH) + kt * 16) * 2));
        #pragma unroll
        for (int nip = 0; nip < 4; ++nip) {
            uint32_t b0, b1, b2, b3;
            ldsm4(b0, b1, b2, b3, WsS + (uint32_t)(((nip * 16 * PH) + kt * 16) * 2));
            #pragma unroll
            for (int mi = 0; mi < 2; ++mi) {
                mma16(o[mi][2 * nip][0], o[mi][2 * nip][1],
                      o[mi][2 * nip][2], o[mi][2 * nip][3],
                      a[mi][0], a[mi][1], a[mi][2], a[mi][3], b0, b1);
                mma16(o[mi][2 * nip + 1][0], o[mi][2 * nip + 1][1],
                      o[mi][2 * nip + 1][2], o[mi][2 * nip + 1][3],
                      a[mi][0], a[mi][1], a[mi][2], a[mi][3], b2, b3);
            }
        }
    }

    // 1/sqrt(512) * log2(e): softmax computed in base-2
    const float qscale = 0.06375863286367196f;
    if (which == 0) {
        #pragma unroll
        for (int mi = 0; mi < 2; ++mi) {
            int r = r0 + 32 * wm + 16 * mi + gid;
            #pragma unroll
            for (int ni = 0; ni < 8; ++ni) {
                int c = ni * 8 + 2 * qid;
                *(uint32_t*)(g_QPh + (size_t)r * HD + c) =
                    f22h(o[mi][ni][0] * qscale, o[mi][ni][1] * qscale);
                *(uint32_t*)(g_QPh + (size_t)(r + 8) * HD + c) =
                    f22h(o[mi][ni][2] * qscale, o[mi][ni][3] * qscale);
            }
        }
    } else {
        // V: transpose through smem, then fully-coalesced row-major stores
        const int bh = r0 >> 11;
        const size_t base = (size_t)bh * HD * SEQ;
        const int l0 = (r0 & 2047);
        __half* Vt = (__half*)smraw;               // 64 x VT_P halves (17.4 KB, fits)
        __syncthreads();
        #pragma unroll
        for (int mi = 0; mi < 2; ++mi) {
            int l = 32 * wm + 16 * mi + gid;
            #pragma unroll
            for (int ni = 0; ni < 8; ++ni) {
                int c = ni * 8 + 2 * qid;
                Vt[c * VT_P + l]           = __float2half_rn(o[mi][ni][0]);
                Vt[(c + 1) * VT_P + l]     = __float2half_rn(o[mi][ni][1]);
                Vt[c * VT_P + l + 8]       = __float2half_rn(o[mi][ni][2]);
                Vt[(c + 1) * VT_P + l + 8] = __float2half_rn(o[mi][ni][3]);
            }
        }
        __syncthreads();
        #pragma unroll
        for (int p = 0; p < 16; ++p) {
            int d = p * 4 + wm;
            uint2 v = *(const uint2*)(Vt + d * VT_P + lane * 4);
            *(uint2*)(g_VPt + base + (size_t)d * SEQ + l0 + lane * 4) = v;
        }
    }
}

// ---------------------------------------------------------------------------
// Kernel 2: fp16 flash attention, no-max softmax, fp16-accum QK,
// nip-outer fused exp2, 5-stage cp.async ring.
// grid (SEQ/128, BH), block 128, dyn smem 92160 B, 2 CTAs/SM.
// ---------------------------------------------------------------------------
__global__ __launch_bounds__(128, 2) void attn_kernel()
{
    extern __shared__ __align__(16) unsigned char smraw[];
    __half* KV = (__half*)smraw;     // STAGES x (K 64xPH + V 64xPH)

    const int tid  = threadIdx.x;
    const int lane = tid & 31, wm = tid >> 5;      // wm 0..3
    const int gid  = lane >> 2, qid = lane & 3;
    const int bh = blockIdx.y;
    const int q0 = blockIdx.x * 128;

    const uint32_t kv_smem = (uint32_t)__cvta_generic_to_shared(KV);
    const int TILE_H = 64 * PH;
    const int TILE_B = TILE_H * 2;       // 9216 B
    const int NT = SEQ / 64;             // 32

    const __half* Kg0 = g_KPh + (size_t)bh * SEQ * HD;
    const __half* Vg0 = g_VPt + (size_t)bh * HD * SEQ;

    const uint32_t lane_off =
        (uint32_t)((((lane & 7) + ((lane >> 4) << 3)) * PH + ((lane >> 3) & 1) * 8) * 2);

    auto prefetch = [&](int tt) {
        uint32_t base = kv_smem + (uint32_t)((tt % STAGES) * 2 * TILE_B);
        const __half* Kg = Kg0 + (size_t)tt * 64 * HD;
        const __half* Vg = Vg0 + tt * 64;
        #pragma unroll
        for (int i = 0; i < 4; ++i) {
            int g = tid + i * 128;
            int row = g >> 3, c8 = g & 7;
            uint32_t off = (uint32_t)(row * 144 + c8 * 16);
            cp16(base + off, Kg + (size_t)row * HD + c8 * 8);
            cp16(base + (uint32_t)TILE_B + off, Vg + (size_t)row * SEQ + c8 * 8);
        }
        cp_commit();
    };

    prefetch(0); prefetch(1); prefetch(2); prefetch(3);

    // Q fragments straight from gmem (pre-scaled half)
    uint32_t qf[2][4][4];
    {
        const __half* Qg = g_QPh + (size_t)(bh * SEQ + q0 + 32 * wm + gid) * HD;
        #pragma unroll
        for (int mi = 0; mi < 2; ++mi) {
            const __half* Qm = Qg + (size_t)(16 * mi) * HD;
            #pragma unroll
            for (int kt = 0; kt < 4; ++kt) {
                int c = kt * 16 + 2 * qid;
                qf[mi][kt][0] = *(const uint32_t*)(Qm + c);
                qf[mi][kt][1] = *(const uint32_t*)(Qm + 8 * HD + c);
                qf[mi][kt][2] = *(const uint32_t*)(Qm + c + 8);
                qf[mi][kt][3] = *(const uint32_t*)(Qm + 8 * HD + c + 8);
            }
        }
    }

    float o[2][8][4];
    #pragma unroll
    for (int mi = 0; mi < 2; ++mi)
        #pragma unroll
        for (int ni = 0; ni < 8; ++ni)
            #pragma unroll
            for (int t = 0; t < 4; ++t) o[mi][ni][t] = 0.f;
    float lsum[2][2] = {{0.f, 0.f}, {0.f, 0.f}};

    for (int t = 0; t < NT; ++t) {
        if (t < NT - 3) cp_wait3();
        else if (t == NT - 3) cp_wait2();
        else if (t == NT - 2) cp_wait1();
        else cp_wait0();
        __syncthreads();

        const int buf = t % STAGES;
        __half* Ks = KV + buf * 2 * TILE_H;
        __half* Vs = Ks + TILE_H;

        if (t + 4 < NT) prefetch(t + 4);

        // ---- S = Q K^T, nip-outer; exp2 fused per column pair ----
        uint32_t sacc[2][8][2];
        const uint32_t KsS = (uint32_t)__cvta_generic_to_shared(Ks) + lane_off;
        #pragma unroll
        for (int nip = 0; nip < 4; ++nip) {
            #pragma unroll
            for (int mi = 0; mi < 2; ++mi) {
                sacc[mi][2 * nip][0] = 0u;     sacc[mi][2 * nip][1] = 0u;
                sacc[mi][2 * nip + 1][0] = 0u; sacc[mi][2 * nip + 1][1] = 0u;
            }
            #pragma unroll
            for (int kt = 0; kt < 4; ++kt) {
                uint32_t b0, b1, b2, b3;
                ldsm4(b0, b1, b2, b3, KsS + (uint32_t)((nip * 16 * PH + kt * 16) * 2));
                #pragma unroll
                for (int mi = 0; mi < 2; ++mi) {
                    mma16h(sacc[mi][2 * nip][0], sacc[mi][2 * nip][1],
                           qf[mi][kt][0], qf[mi][kt][1], qf[mi][kt][2], qf[mi][kt][3], b0, b1);
                    mma16h(sacc[mi][2 * nip + 1][0], sacc[mi][2 * nip + 1][1],
                           qf[mi][kt][0], qf[mi][kt][1], qf[mi][kt][2], qf[mi][kt][3], b2, b3);
                }
            }
            #pragma unroll
            for (int mi = 0; mi < 2; ++mi) {
                sacc[mi][2 * nip][0]     = h2u(h2exp2(u2h(sacc[mi][2 * nip][0])));
                sacc[mi][2 * nip][1]     = h2u(h2exp2(u2h(sacc[mi][2 * nip][1])));
                sacc[mi][2 * nip + 1][0] = h2u(h2exp2(u2h(sacc[mi][2 * nip + 1][0])));
                sacc[mi][2 * nip + 1][1] = h2u(h2exp2(u2h(sacc[mi][2 * nip + 1][1])));
            }
        }

        // ---- O += P V (P in A-fragment layout) ----
        const uint32_t VsS = (uint32_t)__cvta_generic_to_shared(Vs) + lane_off;
        #pragma unroll
        for (int kt = 0; kt < 4; ++kt) {
            #pragma unroll
            for (int nip = 0; nip < 4; ++nip) {
                uint32_t v0, v1, v2, v3;
                ldsm4(v0, v1, v2, v3, VsS + (uint32_t)((nip * 16 * PH + kt * 16) * 2));
                #pragma unroll
                for (int mi = 0; mi < 2; ++mi) {
                    mma16(o[mi][2 * nip][0], o[mi][2 * nip][1],
                          o[mi][2 * nip][2], o[mi][2 * nip][3],
                          sacc[mi][2 * kt][0], sacc[mi][2 * kt][1],
                          sacc[mi][2 * kt + 1][0], sacc[mi][2 * kt + 1][1], v0, v1);
                    mma16(o[mi][2 * nip + 1][0], o[mi][2 * nip + 1][1],
                          o[mi][2 * nip + 1][2], o[mi][2 * nip + 1][3],
                          sacc[mi][2 * kt][0], sacc[mi][2 * kt][1],
                          sacc[mi][2 * kt + 1][0], sacc[mi][2 * kt + 1][1], v2, v3);
                }
            }
        }

        // ---- row-sum partials (overlaps PV drain) ----
        #pragma unroll
        for (int mi = 0; mi < 2; ++mi) {
            __half2 s0t = __hadd2(
                __hadd2(__hadd2(u2h(sacc[mi][0][0]), u2h(sacc[mi][1][0])),
                        __hadd2(u2h(sacc[mi][2][0]), u2h(sacc[mi][3][0]))),
                __hadd2(__hadd2(u2h(sacc[mi][4][0]), u2h(sacc[mi][5][0])),
                        __hadd2(u2h(sacc[mi][6][0]), u2h(sacc[mi][7][0]))));
            __half2 s1t = __hadd2(
                __hadd2(__hadd2(u2h(sacc[mi][0][1]), u2h(sacc[mi][1][1])),
                        __hadd2(u2h(sacc[mi][2][1]), u2h(sacc[mi][3][1]))),
                __hadd2(__hadd2(u2h(sacc[mi][4][1]), u2h(sacc[mi][5][1])),
                        __hadd2(u2h(sacc[mi][6][1]), u2h(sacc[mi][7][1]))));
            float2 s0f = __half22float2(s0t);
            float2 s1f = __half22float2(s1t);
            lsum[mi][0] += s0f.x + s0f.y;
            lsum[mi][1] += s1f.x + s1f.y;
        }
    }

    // epilogue: reduce l across the qid quad, normalize, store half
    const int b = bh >> 3, hh = bh & 7;
    #pragma unroll
    for (int mi = 0; mi < 2; ++mi) {
        float l0 = lsum[mi][0], l1 = lsum[mi][1];
        l0 += __shfl_xor_sync(0xffffffffu, l0, 1);
        l0 += __shfl_xor_sync(0xffffffffu, l0, 2);
        l1 += __shfl_xor_sync(0xffffffffu, l1, 1);
        l1 += __shfl_xor_sync(0xffffffffu, l1, 2);
        const float inv0 = 1.0f / l0;
        const float inv1 = 1.0f / l1;
        const int r = q0 + 32 * wm + 16 * mi + gid;
        #pragma unroll
        for (int ni = 0; ni < 8; ++ni) {
            int c = ni * 8 + 2 * qid;
            *(uint32_t*)(g_AOh + (size_t)(b * SEQ + r) * EMB + hh * HD + c) =
                f22h(o[mi][ni][0] * inv0, o[mi][ni][1] * inv0);
            *(uint32_t*)(g_AOh + (size_t)(b * SEQ + r + 8) * EMB + hh * HD + c) =
                f22h(o[mi][ni][2] * inv1, o[mi][ni][3] * inv1);
        }
    }
}

// ---------------------------------------------------------------------------
// Kernel 3: out = AOh @ Woh^T + bo  (16384 x 512 x 512), fp16 mma.
// tile m128 x n64, block 128, grid (128, 8) = 1024 CTAs, 3 CTAs/SM.
// ---------------------------------------------------------------------------
__global__ __launch_bounds__(128, 3) void out_proj_kernel(
    const float* __restrict__ bo, float* __restrict__ out)
{
    extern __shared__ __align__(16) unsigned char smraw[];
    const int tid  = threadIdx.x;
    const int lane = tid & 31, wm = tid >> 5;
    const int gid  = lane >> 2, qid = lane & 3;
    const int m0 = blockIdx.x * 128;
    const int n0 = blockIdx.y * 64;

    const uint32_t sm0 = (uint32_t)__cvta_generic_to_shared(smraw);
    const int BUF_B = (128 + 64) * 144;   // 27648 B

    auto prefetch = [&](int c) {
        uint32_t base = sm0 + (uint32_t)((c & 1) * BUF_B);
        int k0 = c * 64;
        #pragma unroll
        for (int i = 0; i < 8; ++i) {
            int g = tid + i * 128;
            int row = g >> 3, c8 = g & 7;
            cp16(base + (uint32_t)(row * 144 + c8 * 16),
                 g_AOh + (size_t)(m0 + row) * EMB + k0 + c8 * 8);
        }
        #pragma unroll
        for (int i = 0; i < 4; ++i) {
            int g = tid + i * 128;
            int row = g >> 3, c8 = g & 7;
            cp16(base + (uint32_t)(128 * 144 + row * 144 + c8 * 16),
                 g_Woh + (size_t)(n0 + row) * EMB + k0 + c8 * 8);
        }
        cp_commit();
    };

    prefetch(0);

    float o[2][8][4];
    #pragma unroll
    for (int mi = 0; mi < 2; ++mi)
        #pragma unroll
        for (int ni = 0; ni < 8; ++ni)
            #pragma unroll
            for (int t = 0; t < 4; ++t) o[mi][ni][t] = 0.f;

    const uint32_t laneA = (uint32_t)(((lane & 15) * PH + (lane >> 4) * 8) * 2);
    const uint32_t laneB =
        (uint32_t)((((lane & 7) + ((lane >> 4) << 3)) * PH + ((lane >> 3) & 1) * 8) * 2);

    for (int c = 0; c < 8; ++c) {
        cp_wait0();
        __syncthreads();
        if (c + 1 < 8) prefetch(c + 1);

        uint32_t AsS = sm0 + (uint32_t)((c & 1) * BUF_B) + laneA;
        uint32_t BsS = sm0 + (uint32_t)((c & 1) * BUF_B + 128 * 144) + laneB;

        #pragma unroll
        for (int kt = 0; kt < 4; ++kt) {
            uint32_t a[2][4];
            #pragma unroll
            for (int mi = 0; mi < 2; ++mi)
                ldsm4(a[mi][0], a[mi][1], a[mi][2], a[mi][3],
                      AsS + (uint32_t)((((32 * wm + 16 * mi) * PH) + kt * 16) * 2));
            #pragma unroll
            for (int nip = 0; nip < 4; ++nip) {
                uint32_t b0, b1, b2, b3;
                ldsm4(b0, b1, b2, b3,
                      BsS + (uint32_t)(((nip * 16 * PH) + kt * 16) * 2));
                #pragma unroll
                for (int mi = 0; mi < 2; ++mi) {
                    mma16(o[mi][2 * nip][0], o[mi][2 * nip][1],
                          o[mi][2 * nip][2], o[mi][2 * nip][3],
                          a[mi][0], a[mi][1], a[mi][2], a[mi][3], b0, b1);
                    mma16(o[mi][2 * nip + 1][0], o[mi][2 * nip + 1][1],
                          o[mi][2 * nip + 1][2], o[mi][2 * nip + 1][3],
                          a[mi][0], a[mi][1], a[mi][2], a[mi][3], b2, b3);
                }
            }
        }
    }

    #pragma unroll
    for (int mi = 0; mi < 2; ++mi) {
        int r = m0 + 32 * wm + 16 * mi + gid;
        #pragma unroll
        for (int ni = 0; ni < 8; ++ni) {
            int cc = n0 + ni * 8 + 2 * qid;
            float bb0 = bo[cc], bb1 = bo[cc + 1];
            *(float2*)(out + (size_t)r * EMB + cc) =
                make_float2(o[mi][ni][0] + bb0, o[mi][ni][1] + bb1);
            *(float2*)(out + (size_t)(r + 8) * EMB + cc) =
                make_float2(o[mi][ni][2] + bb0, o[mi][ni][3] + bb1);
        }
    }
}

// ---------------------------------------------------------------------------
extern "C" void kernel_launch(void* const* d_in, const int* in_sizes, int n_in,
                              void* d_out, int out_size)
{
    const float* q  = (const float*)d_in[0];
    const float* k  = (const float*)d_in[1];
    const float* v  = (const float*)d_in[2];
    const float* Wq = (const float*)d_in[3];
    const float* Wk = (const float*)d_in[4];
    const float* Wv = (const float*)d_in[5];
    const float* Wo = (const float*)d_in[6];
    const float* bo = (const float*)d_in[7];
    float* out = (float*)d_out;

    const int proj_smem  = (128 + 64) * PH * 2;                   // 27648
    const int attn_smem  = STAGES * 2 * 64 * PH * 2;              // 92160
    const int oproj_smem = 2 * (128 + 64) * 144;                  // 55296

    cudaFuncSetAttribute(proj_kernel, cudaFuncAttributeMaxDynamicSharedMemorySize, proj_smem);
    cudaFuncSetAttribute(attn_kernel, cudaFuncAttributeMaxDynamicSharedMemorySize, attn_smem);
    cudaFuncSetAttribute(out_proj_kernel, cudaFuncAttributeMaxDynamicSharedMemorySize, oproj_smem);

    setup_kernel<<<272, 256>>>(Wo, Wq, Wk);
    proj_kernel<<<dim3(NROWS / 128, 3, 1), 128, proj_smem>>>(q, k, v, Wv);
    attn_kernel<<<dim3(SEQ / 128, BH, 1), 128, attn_smem>>>();
    out_proj_kernel<<<dim3((NB * SEQ) / 128, EMB / 64, 1), 128, oproj_smem>>>(bo, out);
}